// round 13
// baseline (speedup 1.0000x reference)
#include <cuda_runtime.h>
#include <cuda.h>
#include <cuda_bf16.h>
#include <math.h>
#include <cstdint>
#include <cstring>

#define SEQ 2048
#define DIM 2048
#define NH 16
#define HDIM 128

// ------------------------- scratch (device globals) -------------------------
__device__ float g_G[SEQ * DIM];
__device__ float g_Y[SEQ * DIM];

__device__ __nv_bfloat16 g_xhi[SEQ * DIM],  g_xlo[SEQ * DIM];
__device__ __nv_bfloat16 g_wqhi[DIM * DIM], g_wqlo[DIM * DIM];
__device__ __nv_bfloat16 g_wkhi[DIM * DIM], g_wklo[DIM * DIM];
__device__ __nv_bfloat16 g_wvhi[DIM * DIM], g_wvlo[DIM * DIM];
__device__ __nv_bfloat16 g_wghi[DIM * DIM], g_wglo[DIM * DIM];
__device__ __nv_bfloat16 g_wohi[DIM * DIM], g_wolo[DIM * DIM];
__device__ __nv_bfloat16 g_Qhi[SEQ * DIM],  g_Qlo[SEQ * DIM];
__device__ __nv_bfloat16 g_Khi[SEQ * DIM],  g_Klo[SEQ * DIM];
__device__ __nv_bfloat16 g_Vhi[SEQ * DIM],  g_Vlo[SEQ * DIM];
__device__ __nv_bfloat16 g_ahi[SEQ * DIM],  g_alo[SEQ * DIM];

__device__ CUtensorMap g_tmaps[14];

// ------------------------- helpers -------------------------
__device__ __forceinline__ uint32_t smem_u32(const void* p) {
    uint32_t a;
    asm("{ .reg .u64 t; cvta.to.shared.u64 t, %1; cvt.u32.u64 %0, t; }" : "=r"(a) : "l"(p));
    return a;
}
__device__ __forceinline__ void cp16(uint32_t dst, const void* src) {
    asm volatile("cp.async.cg.shared.global [%0], [%1], 16;" :: "r"(dst), "l"(src));
}
__device__ __forceinline__ void ldx4(uint32_t* r, uint32_t addr) {
    asm volatile("ldmatrix.sync.aligned.m8n8.x4.shared.b16 {%0,%1,%2,%3}, [%4];"
                 : "=r"(r[0]), "=r"(r[1]), "=r"(r[2]), "=r"(r[3]) : "r"(addr));
}
__device__ __forceinline__ void ldx4t(uint32_t* r, uint32_t addr) {
    asm volatile("ldmatrix.sync.aligned.m8n8.x4.trans.shared.b16 {%0,%1,%2,%3}, [%4];"
                 : "=r"(r[0]), "=r"(r[1]), "=r"(r[2]), "=r"(r[3]) : "r"(addr));
}
__device__ __forceinline__ void mma16816(float* c, const uint32_t* a, uint32_t b0, uint32_t b1) {
    asm volatile(
        "mma.sync.aligned.m16n8k16.row.col.f32.bf16.bf16.f32 "
        "{%0,%1,%2,%3}, {%4,%5,%6,%7}, {%8,%9}, {%0,%1,%2,%3};"
        : "+f"(c[0]), "+f"(c[1]), "+f"(c[2]), "+f"(c[3])
        : "r"(a[0]), "r"(a[1]), "r"(a[2]), "r"(a[3]), "r"(b0), "r"(b1));
}

#define MBARRIER_INIT(addr, cnt) \
    asm volatile("mbarrier.init.shared.b64 [%0], %1;" :: "r"(addr), "r"(cnt) : "memory")
#define MBARRIER_ARRIVE(addr) \
    asm volatile("mbarrier.arrive.shared.b64 _, [%0];" :: "r"(addr) : "memory")
#define MBARRIER_EXPECT_TX(addr, bytes) \
    asm volatile("mbarrier.arrive.expect_tx.shared.b64 _, [%0], %1;" :: "r"(addr), "r"(bytes) : "memory")
#define MBARRIER_WAIT_PARITY(addr, par) do { \
    uint32_t _m = (addr); uint32_t _p = (par); uint32_t _d; \
    asm volatile("{ .reg .pred p; mbarrier.try_wait.parity.acquire.cta.shared::cta.b64 p, [%1], %2; selp.b32 %0,1,0,p; }" \
        : "=r"(_d) : "r"(_m), "r"(_p) : "memory"); \
    if (!_d) { \
        asm volatile("{ .reg .pred P1; WL_%=: mbarrier.try_wait.parity.acquire.cta.shared::cta.b64 P1, [%0], %1, 0x989680; @P1 bra.uni WD_%=; bra.uni WL_%=; WD_%=: }" \
            :: "r"(_m), "r"(_p) : "memory"); \
    } \
} while (0)
#define TMA_LOAD_2D(smem_addr, map, cx, cy, mbar) \
    asm volatile("cp.async.bulk.tensor.2d.shared::cta.global.tile.mbarrier::complete_tx::bytes " \
                 "[%0], [%1, {%2, %3}], [%4];" \
                 :: "r"(smem_addr), "l"(map), "r"(cx), "r"(cy), "r"(mbar) : "memory")

// ---------------------------------------------------------------------------
// Fused 3-pass hi/lo bf16 GEMM (TN). Tile 128x256, BK=64, 512 threads (4x4).
// TMA + full/empty mbarrier ring; per-warp empty arrives; alternating producer.
// ---------------------------------------------------------------------------
static constexpr int GBM = 128, GBN = 256, GBK = 64;
static constexpr int GTHREADS = 512;
static constexpr int NCH = DIM / GBK;
static constexpr int OF_AH = 0;
static constexpr int OF_AL = 16384;
static constexpr int OF_BH = 32768;
static constexpr int OF_BL = 65536;
static constexpr int GBUF = 98304;
static constexpr int GEMM_SMEM = 2 * GBUF + 64;

__device__ __forceinline__ void tma_chunk(uint32_t buf, const CUtensorMap* mAh,
                                          const CUtensorMap* mAl, const CUtensorMap* mBh,
                                          const CUtensorMap* mBl, int m0, int n0, int kc,
                                          uint32_t bar) {
    MBARRIER_EXPECT_TX(bar, (uint32_t)GBUF);
    TMA_LOAD_2D(buf + OF_AH, mAh, kc, m0, bar);
    TMA_LOAD_2D(buf + OF_AL, mAl, kc, m0, bar);
    TMA_LOAD_2D(buf + OF_BH, mBh, kc, n0, bar);
    TMA_LOAD_2D(buf + OF_BL, mBl, kc, n0, bar);
}

__global__ __launch_bounds__(GTHREADS, 1) void gemm3(const CUtensorMap* __restrict__ mAh,
                                                     const CUtensorMap* __restrict__ mAl,
                                                     const CUtensorMap* __restrict__ mBh,
                                                     const CUtensorMap* __restrict__ mBl,
                                                     float* __restrict__ C,
                                                     __nv_bfloat16* __restrict__ Chi,
                                                     __nv_bfloat16* __restrict__ Clo,
                                                     int mode) {
    extern __shared__ char smem[];
    uint32_t sb = smem_u32(smem);
    uint32_t full0 = sb + 2 * GBUF, full1 = full0 + 8;
    uint32_t empty0 = full1 + 8, empty1 = empty0 + 8;
    int tid = threadIdx.x;
    int wid = tid >> 5, lane = tid & 31;
    int wm = wid & 3, wn = wid >> 2;
    int m0 = blockIdx.y * GBM, n0 = blockIdx.x * GBN;

    if (tid == 0) {
        asm volatile("prefetch.tensormap [%0];" :: "l"(mAh));
        asm volatile("prefetch.tensormap [%0];" :: "l"(mAl));
        asm volatile("prefetch.tensormap [%0];" :: "l"(mBh));
        asm volatile("prefetch.tensormap [%0];" :: "l"(mBl));
        MBARRIER_INIT(full0, 1);
        MBARRIER_INIT(full1, 1);
        MBARRIER_INIT(empty0, 16);
        MBARRIER_INIT(empty1, 16);
    }
    __syncthreads();
    if (tid == 0) {
        tma_chunk(sb, mAh, mAl, mBh, mBl, m0, n0, 0, full0);
        tma_chunk(sb + GBUF, mAh, mAl, mBh, mBl, m0, n0, GBK, full1);
    }

    int a_mh = (lane >> 3) & 1, a_kh = lane >> 4, lr = lane & 7;
    uint32_t aOff[2]; int aR7[2];
#pragma unroll
    for (int i = 0; i < 2; i++) {
        int row = wm * 32 + i * 16 + a_mh * 8 + lr;
        aOff[i] = row * 128; aR7[i] = row & 7;
    }
    int b_jl = lane >> 4, b_kh = (lane >> 3) & 1;
    uint32_t bOff[4]; int bR7[4];
#pragma unroll
    for (int p = 0; p < 4; p++) {
        int row = wn * 64 + p * 16 + b_jl * 8 + lr;
        bOff[p] = row * 128; bR7[p] = row & 7;
    }

    float acc[2][8][4];
#pragma unroll
    for (int i = 0; i < 2; i++)
#pragma unroll
        for (int j = 0; j < 8; j++)
#pragma unroll
            for (int q = 0; q < 4; q++) acc[i][j][q] = 0.f;

    for (int t = 0; t < NCH; t++) {
        uint32_t full  = (t & 1) ? full1 : full0;
        uint32_t empty = (t & 1) ? empty1 : empty0;
        MBARRIER_WAIT_PARITY(full, (t >> 1) & 1);

        uint32_t buf = sb + (t & 1) * GBUF;
#pragma unroll
        for (int ks = 0; ks < 4; ks++) {
            int ca = ks * 2 + a_kh;
            int cb = ks * 2 + b_kh;
            uint32_t ah[2][4], bh[4][4], bl[4][4];
#pragma unroll
            for (int i = 0; i < 2; i++)
                ldx4(ah[i], buf + OF_AH + aOff[i] + (((uint32_t)(ca ^ aR7[i])) << 4));
#pragma unroll
            for (int p = 0; p < 4; p++) {
                ldx4(bh[p], buf + OF_BH + bOff[p] + (((uint32_t)(cb ^ bR7[p])) << 4));
                ldx4(bl[p], buf + OF_BL + bOff[p] + (((uint32_t)(cb ^ bR7[p])) << 4));
            }
#pragma unroll
            for (int i = 0; i < 2; i++)
#pragma unroll
                for (int j = 0; j < 8; j++) {
                    int p = j >> 1, jl = j & 1;
                    mma16816(acc[i][j], ah[i], bh[p][2 * jl], bh[p][2 * jl + 1]);
                    mma16816(acc[i][j], ah[i], bl[p][2 * jl], bl[p][2 * jl + 1]);
                }
            uint32_t al[2][4];
#pragma unroll
            for (int i = 0; i < 2; i++)
                ldx4(al[i], buf + OF_AL + aOff[i] + (((uint32_t)(ca ^ aR7[i])) << 4));
#pragma unroll
            for (int i = 0; i < 2; i++)
#pragma unroll
                for (int j = 0; j < 8; j++) {
                    int p = j >> 1, jl = j & 1;
                    mma16816(acc[i][j], al[i], bh[p][2 * jl], bh[p][2 * jl + 1]);
                }
        }

        if (lane == 0) MBARRIER_ARRIVE(empty);        // per-warp consume signal
        if (t + 2 < NCH && tid == ((t & 1) << 5)) {   // alternate producer warp
            MBARRIER_WAIT_PARITY(empty, (t >> 1) & 1);
            tma_chunk(buf, mAh, mAl, mBh, mBl, m0, n0, (t + 2) * GBK, full);
        }
    }

    int qr = lane >> 2, qc = (lane & 3) * 2;
#pragma unroll
    for (int i = 0; i < 2; i++) {
        int mrow = m0 + wm * 32 + i * 16 + qr;
#pragma unroll
        for (int j = 0; j < 8; j++) {
            size_t base = (size_t)mrow * DIM + n0 + wn * 64 + j * 8 + qc;
            if (mode == 0) {
                C[base]               = acc[i][j][0];
                C[base + 1]           = acc[i][j][1];
                C[base + 8 * DIM]     = acc[i][j][2];
                C[base + 8 * DIM + 1] = acc[i][j][3];
            } else {
#pragma unroll
                for (int h2 = 0; h2 < 2; h2++) {
                    float v0 = acc[i][j][h2 * 2], v1 = acc[i][j][h2 * 2 + 1];
                    __nv_bfloat16 h0 = __float2bfloat16(v0), h1 = __float2bfloat16(v1);
                    __nv_bfloat16 l0 = __float2bfloat16(v0 - __bfloat162float(h0));
                    __nv_bfloat16 l1 = __float2bfloat16(v1 - __bfloat162float(h1));
                    size_t bb = base + h2 * 8 * DIM;
                    *(__nv_bfloat162*)(Chi + bb) = __nv_bfloat162(h0, h1);
                    *(__nv_bfloat162*)(Clo + bb) = __nv_bfloat162(l0, l1);
                }
            }
        }
    }
}

// ---------------------------------------------------------------------------
// fp32 -> bf16 hi/lo, all 6 tensors in one launch
// ---------------------------------------------------------------------------
__global__ __launch_bounds__(256) void cvt6(
    const float* s0, __nv_bfloat16* h0, __nv_bfloat16* l0,
    const float* s1, __nv_bfloat16* h1, __nv_bfloat16* l1,
    const float* s2, __nv_bfloat16* h2, __nv_bfloat16* l2,
    const float* s3, __nv_bfloat16* h3, __nv_bfloat16* l3,
    const float* s4, __nv_bfloat16* h4, __nv_bfloat16* l4,
    const float* s5, __nv_bfloat16* h5, __nv_bfloat16* l5) {
    const float* s; __nv_bfloat16 *hi, *lo;
    switch (blockIdx.y) {
        case 0: s = s0; hi = h0; lo = l0; break;
        case 1: s = s1; hi = h1; lo = l1; break;
        case 2: s = s2; hi = h2; lo = l2; break;
        case 3: s = s3; hi = h3; lo = l3; break;
        case 4: s = s4; hi = h4; lo = l4; break;
        default: s = s5; hi = h5; lo = l5; break;
    }
    int base = blockIdx.x * 1024 + threadIdx.x;
    float4 v[4];
#pragma unroll
    for (int u = 0; u < 4; u++) v[u] = ((const float4*)s)[base + u * 256];
#pragma unroll
    for (int u = 0; u < 4; u++) {
        int i = base + u * 256;
        __nv_bfloat16 a0 = __float2bfloat16(v[u].x), a1 = __float2bfloat16(v[u].y);
        __nv_bfloat16 a2 = __float2bfloat16(v[u].z), a3 = __float2bfloat16(v[u].w);
        __nv_bfloat16 b0 = __float2bfloat16(v[u].x - __bfloat162float(a0));
        __nv_bfloat16 b1 = __float2bfloat16(v[u].y - __bfloat162float(a1));
        __nv_bfloat16 b2 = __float2bfloat16(v[u].z - __bfloat162float(a2));
        __nv_bfloat16 b3 = __float2bfloat16(v[u].w - __bfloat162float(a3));
        ((__nv_bfloat162*)hi)[2 * i]     = __nv_bfloat162(a0, a1);
        ((__nv_bfloat162*)hi)[2 * i + 1] = __nv_bfloat162(a2, a3);
        ((__nv_bfloat162*)lo)[2 * i]     = __nv_bfloat162(b0, b1);
        ((__nv_bfloat162*)lo)[2 * i + 1] = __nv_bfloat162(b2, b3);
    }
}

// ---------------------------------------------------------------------------
// Tensor-core retention attention, BI=128, BJ=64, 512 threads (16 warps, 4x4).
// K double-buffered (prefetch), V single-buffered (loads overlap stage 1).
// grid (16 i-tiles, 16 heads).
// ---------------------------------------------------------------------------
static constexpr int A_OQH = 0, A_OQL = 32768;
static constexpr int A_OK  = 65536;      // + stage*32768 ; Kh +0, Kl +16384
static constexpr int A_OV  = 131072;     // Vh +0, Vl +16384
static constexpr int A_OS  = 163840;     // Sh +0, Sl +16384
static constexpr int AT_SMEM = 196608;   // 192 KB

__global__ __launch_bounds__(512, 1) void retention_tc() {
    extern __shared__ char smem[];
    uint32_t sb = smem_u32(smem);

    int head = blockIdx.y;
    int it = gridDim.x - 1 - blockIdx.x;   // heaviest first
    int i0 = it * 128;
    int tid = threadIdx.x, lane = tid & 31, wid = tid >> 5;
    int wm = wid & 3, wn = wid >> 2;

    const float lg0 = -3.4657359027997265f;
    const float lg1 = -6.2383246250395075f;
    float gamma = 1.0f - expf(lg0 + (lg1 - lg0) * ((float)head * (1.0f / 15.0f)));
    float log2g = log2f(gamma);
    const float scale = 0.088388347648318447f;

    const __nv_bfloat16* Qhg = g_Qhi + head * HDIM;
    const __nv_bfloat16* Qlg = g_Qlo + head * HDIM;
    const __nv_bfloat16* Khg = g_Khi + head * HDIM;
    const __nv_bfloat16* Klg = g_Klo + head * HDIM;
    const __nv_bfloat16* Vhg = g_Vhi + head * HDIM;
    const __nv_bfloat16* Vlg = g_Vlo + head * HDIM;

    int qr = lane >> 2, qc = (lane & 3) * 2;
    int a_mh = (lane >> 3) & 1, a_kh = lane >> 4, lr = lane & 7;
    int b_jl = lane >> 4, b_kh = (lane >> 3) & 1;
    int v_m = (lane >> 3) & 1, v_g = lane >> 4;

    uint32_t aOff[2]; int aR7[2];
#pragma unroll
    for (int i = 0; i < 2; i++) {
        int row = wm * 32 + i * 16 + a_mh * 8 + lr;
        aOff[i] = row * 128; aR7[i] = row & 7;
    }
    int brow = wn * 16 + b_jl * 8 + lr;
    uint32_t bOff = brow * 128; int bR7 = brow & 7;

    float colfac[2][2];
#pragma unroll
    for (int jf = 0; jf < 2; jf++)
#pragma unroll
        for (int lb = 0; lb < 2; lb++) {
            int dj = wn * 16 + jf * 8 + qc + lb;
            colfac[jf][lb] = exp2f(-log2g * (float)dj) * scale;
        }

    // prologue: Q (hi/lo, 128x128) + K tile 0, one commit group
#pragma unroll
    for (int l = 0; l < 8; l++) {
        int idx = tid + l * 512;
        int arr = idx >> 11, r = (idx >> 4) & 127, c = idx & 15;
        int ct = c >> 3, c7 = c & 7;
        const __nv_bfloat16* src = (arr ? Qlg : Qhg) + (size_t)(i0 + r) * DIM + ct * 64 + c7 * 8;
        uint32_t dst = sb + (arr ? A_OQL : A_OQH) + ct * 16384 + r * 128 + (((c7 ^ (r & 7))) << 4);
        cp16(dst, src);
    }
#pragma unroll
    for (int l = 0; l < 4; l++) {
        int idx = tid + l * 512;
        int arr = idx >> 10, r = (idx >> 4) & 63, c = idx & 15;
        int ct = c >> 3, c7 = c & 7;
        const __nv_bfloat16* src = (arr ? Klg : Khg) + (size_t)r * DIM + ct * 64 + c7 * 8;
        uint32_t dst = sb + A_OK + arr * 16384 + ct * 8192 + r * 128 + (((c7 ^ (r & 7))) << 4);
        cp16(dst, src);
    }
    asm volatile("cp.async.commit_group;" ::: "memory");

    float yacc[2][4][4];
#pragma unroll
    for (int i = 0; i < 2; i++)
#pragma unroll
        for (int t = 0; t < 4; t++)
#pragma unroll
            for (int q = 0; q < 4; q++) yacc[i][t][q] = 0.f;

    int njt = 2 * it + 2;
    for (int jt = 0; jt < njt; jt++) {
        int j0 = jt * 64;
        uint32_t kb = sb + A_OK + (jt & 1) * 32768;

        asm volatile("cp.async.wait_group 0;" ::: "memory");  // K(jt) (+Q on jt==0)
        __syncthreads();   // stage2(jt-1) done: V & S free; K(jt) visible

        // V(jt) -> single V buffer (overlaps stage 1)
#pragma unroll
        for (int l = 0; l < 4; l++) {
            int idx = tid + l * 512;
            int arr = idx >> 10, r = (idx >> 4) & 63, dc = idx & 15;
            const __nv_bfloat16* src = (arr ? Vlg : Vhg) + (size_t)(j0 + r) * DIM + dc * 8;
            uint32_t dst = sb + A_OV + arr * 16384 + r * 256 + (((dc ^ (r & 7))) << 4);
            cp16(dst, src);
        }
        asm volatile("cp.async.commit_group;" ::: "memory");
        bool pf = (jt + 1 < njt);
        if (pf) {  // prefetch K(jt+1) into alternate K buffer
            uint32_t kb2 = sb + A_OK + ((jt + 1) & 1) * 32768;
#pragma unroll
            for (int l = 0; l < 4; l++) {
                int idx = tid + l * 512;
                int arr = idx >> 10, r = (idx >> 4) & 63, c = idx & 15;
                int ct = c >> 3, c7 = c & 7;
                const __nv_bfloat16* src = (arr ? Klg : Khg) + (size_t)(j0 + 64 + r) * DIM + ct * 64 + c7 * 8;
                uint32_t dst = kb2 + arr * 16384 + ct * 8192 + r * 128 + (((c7 ^ (r & 7))) << 4);
                cp16(dst, src);
            }
            asm volatile("cp.async.commit_group;" ::: "memory");
        }

        // ---- stage 1: S = Q.K^T (3-pass hi/lo) ----
        float acc1[2][2][4];
#pragma unroll
        for (int i = 0; i < 2; i++)
#pragma unroll
            for (int j = 0; j < 2; j++)
#pragma unroll
                for (int q = 0; q < 4; q++) acc1[i][j][q] = 0.f;

#pragma unroll
        for (int ct = 0; ct < 2; ct++) {
#pragma unroll
            for (int ks = 0; ks < 4; ks++) {
                int ca = ks * 2 + a_kh;
                int cb = ks * 2 + b_kh;
                uint32_t qh[2][4], ql[2][4], bh[4], bl[4];
#pragma unroll
                for (int i = 0; i < 2; i++) {
                    ldx4(qh[i], sb + A_OQH + ct * 16384 + aOff[i] + (((uint32_t)(ca ^ aR7[i])) << 4));
                    ldx4(ql[i], sb + A_OQL + ct * 16384 + aOff[i] + (((uint32_t)(ca ^ aR7[i])) << 4));
                }
                ldx4(bh, kb + ct * 8192 + bOff + (((uint32_t)(cb ^ bR7)) << 4));
                ldx4(bl, kb + 16384 + ct * 8192 + bOff + (((uint32_t)(cb ^ bR7)) << 4));
#pragma unroll
                for (int i = 0; i < 2; i++)
#pragma unroll
                    for (int j = 0; j < 2; j++) {
                        mma16816(acc1[i][j], qh[i], bh[2 * j], bh[2 * j + 1]);
                        mma16816(acc1[i][j], qh[i], bl[2 * j], bl[2 * j + 1]);
                        mma16816(acc1[i][j], ql[i], bh[2 * j], bh[2 * j + 1]);
                    }
            }
        }

        // ---- decay, mask, split -> S smem ----
        float rowfac[2][2];
#pragma unroll
        for (int i = 0; i < 2; i++)
#pragma unroll
            for (int h = 0; h < 2; h++) {
                int rrel = i0 - j0 + wm * 32 + i * 16 + qr + h * 8;
                rowfac[i][h] = exp2f(log2g * (float)rrel);
            }
#pragma unroll
        for (int i = 0; i < 2; i++)
#pragma unroll
            for (int j = 0; j < 2; j++)
#pragma unroll
                for (int h = 0; h < 2; h++) {
                    int row = wm * 32 + i * 16 + qr + h * 8;
                    int col = wn * 16 + j * 8 + qc;
                    int diff0 = (i0 + row) - (j0 + col);
                    float v0 = (diff0 >= 0) ? acc1[i][j][h * 2 + 0] * rowfac[i][h] * colfac[j][0] : 0.f;
                    float v1 = (diff0 >= 1) ? acc1[i][j][h * 2 + 1] * rowfac[i][h] * colfac[j][1] : 0.f;
                    __nv_bfloat16 h0 = __float2bfloat16(v0), h1 = __float2bfloat16(v1);
                    __nv_bfloat16 l0 = __float2bfloat16(v0 - __bfloat162float(h0));
                    __nv_bfloat16 l1 = __float2bfloat16(v1 - __bfloat162float(h1));
                    uint32_t off = row * 128 + ((((col >> 3) ^ (row & 7))) << 4) + (col & 7) * 2;
                    *(__nv_bfloat162*)(smem + A_OS + off)         = __nv_bfloat162(h0, h1);
                    *(__nv_bfloat162*)(smem + A_OS + 16384 + off) = __nv_bfloat162(l0, l1);
                }

        // wait V(jt) (K(jt+1) may stay outstanding); publish S
        if (pf) { asm volatile("cp.async.wait_group 1;" ::: "memory"); }
        else    { asm volatile("cp.async.wait_group 0;" ::: "memory"); }
        __syncthreads();

        // ---- stage 2: Y += S.V (3-pass hi/lo) ----
#pragma unroll
        for (int ks = 0; ks < 4; ks++) {
            int ca = ks * 2 + a_kh;
            uint32_t sh[2][4], sl[2][4], vh[2][4], vl[2][4];
#pragma unroll
            for (int i = 0; i < 2; i++) {
                ldx4(sh[i], sb + A_OS + aOff[i] + (((uint32_t)(ca ^ aR7[i])) << 4));
                ldx4(sl[i], sb + A_OS + 16384 + aOff[i] + (((uint32_t)(ca ^ aR7[i])) << 4));
            }
            int vrow = ks * 16 + v_m * 8 + lr;
#pragma unroll
            for (int g = 0; g < 2; g++) {
                int dc = wn * 4 + g * 2 + v_g;
                uint32_t vo = vrow * 256 + (((uint32_t)(dc ^ (vrow & 7))) << 4);
                ldx4t(vh[g], sb + A_OV + vo);
                ldx4t(vl[g], sb + A_OV + 16384 + vo);
            }
#pragma unroll
            for (int i = 0; i < 2; i++)
#pragma unroll
                for (int t = 0; t < 4; t++) {
                    int g = t >> 1, s2 = (t & 1) * 2;
                    mma16816(yacc[i][t], sh[i], vh[g][s2], vh[g][s2 + 1]);
                    mma16816(yacc[i][t], sh[i], vl[g][s2], vl[g][s2 + 1]);
                    mma16816(yacc[i][t], sl[i], vh[g][s2], vh[g][s2 + 1]);
                }
        }
    }

    // epilogue -> g_Y fp32
#pragma unroll
    for (int i = 0; i < 2; i++) {
        int row = i0 + wm * 32 + i * 16 + qr;
#pragma unroll
        for (int t = 0; t < 4; t++) {
            float* yp = g_Y + (size_t)row * DIM + head * HDIM + wn * 32 + t * 8 + qc;
            *(float2*)yp = make_float2(yacc[i][t][0], yacc[i][t][1]);
            *(float2*)(yp + 8 * DIM) = make_float2(yacc[i][t][2], yacc[i][t][3]);
        }
    }
}

// ---------------------------------------------------------------------------
// LayerNorm(Y) * silu(G) -> bf16 hi + lo arrays
// ---------------------------------------------------------------------------
__global__ __launch_bounds__(256) void ln_silu_gate(const float* __restrict__ lnw,
                                                    const float* __restrict__ lnb,
                                                    __nv_bfloat16* __restrict__ ohi,
                                                    __nv_bfloat16* __restrict__ olo) {
    int row = blockIdx.x;
    const float* y = g_Y + (size_t)row * DIM;
    const float* g = g_G + (size_t)row * DIM;
    int tid = threadIdx.x;

    float vals[8];
    float s = 0.f, ss = 0.f;
#pragma unroll
    for (int i = 0; i < 2; i++) {
        float4 v = *(const float4*)(y + tid * 4 + i * 1024);
        vals[i * 4 + 0] = v.x; vals[i * 4 + 1] = v.y;
        vals[i * 4 + 2] = v.z; vals[i * 4 + 3] = v.w;
        s += v.x + v.y + v.z + v.w;
        ss += v.x * v.x + v.y * v.y + v.z * v.z + v.w * v.w;
    }
#pragma unroll
    for (int off = 16; off > 0; off >>= 1) {
        s += __shfl_xor_sync(0xFFFFFFFFu, s, off);
        ss += __shfl_xor_sync(0xFFFFFFFFu, ss, off);
    }
    __shared__ float rs[8], rss[8];
    if ((tid & 31) == 0) { rs[tid >> 5] = s; rss[tid >> 5] = ss; }
    __syncthreads();
    s = 0.f; ss = 0.f;
#pragma unroll
    for (int i = 0; i < 8; i++) { s += rs[i]; ss += rss[i]; }

    float mu = s * (1.0f / DIM);
    float var = ss * (1.0f / DIM) - mu * mu;
    float rstd = rsqrtf(var + 1e-5f);

#pragma unroll
    for (int i = 0; i < 2; i++) {
        int c0 = tid * 4 + i * 1024;
        float4 gv = *(const float4*)(g + c0);
        float4 wv = *(const float4*)(lnw + c0);
        float4 bv = *(const float4*)(lnb + c0);
        float o[4];
        o[0] = ((vals[i * 4 + 0] - mu) * rstd * wv.x + bv.x) * (gv.x / (1.0f + expf(-gv.x)));
        o[1] = ((vals[i * 4 + 1] - mu) * rstd * wv.y + bv.y) * (gv.y / (1.0f + expf(-gv.y)));
        o[2] = ((vals[i * 4 + 2] - mu) * rstd * wv.z + bv.z) * (gv.z / (1.0f + expf(-gv.z)));
        o[3] = ((vals[i * 4 + 3] - mu) * rstd * wv.w + bv.w) * (gv.w / (1.0f + expf(-gv.w)));
        __nv_bfloat16 h[4], l[4];
#pragma unroll
        for (int j = 0; j < 4; j++) {
            h[j] = __float2bfloat16(o[j]);
            l[j] = __float2bfloat16(o[j] - __bfloat162float(h[j]));
        }
        size_t base = (size_t)row * DIM + c0;
        *(__nv_bfloat162*)(ohi + base)     = __nv_bfloat162(h[0], h[1]);
        *(__nv_bfloat162*)(ohi + base + 2) = __nv_bfloat162(h[2], h[3]);
        *(__nv_bfloat162*)(olo + base)     = __nv_bfloat162(l[0], l[1]);
        *(__nv_bfloat162*)(olo + base + 2) = __nv_bfloat162(l[2], l[3]);
    }
}

// ---------------------------------------------------------------------------
typedef CUresult (*EncodeFn)(CUtensorMap*, CUtensorMapDataType, cuuint32_t, void*,
                             const cuuint64_t*, const cuuint64_t*, const cuuint32_t*,
                             const cuuint32_t*, CUtensorMapInterleave, CUtensorMapSwizzle,
                             CUtensorMapL2promotion, CUtensorMapFloatOOBfill);

static void make_map2d(EncodeFn enc, CUtensorMap* m, void* ptr, uint32_t box_rows) {
    cuuint64_t dims[2] = {DIM, SEQ};
    cuuint64_t strides[1] = {DIM * 2};
    cuuint32_t box[2] = {64, box_rows};
    cuuint32_t es[2] = {1, 1};
    enc(m, CU_TENSOR_MAP_DATA_TYPE_BFLOAT16, 2, ptr, dims, strides, box, es,
        CU_TENSOR_MAP_INTERLEAVE_NONE, CU_TENSOR_MAP_SWIZZLE_128B,
        CU_TENSOR_MAP_L2_PROMOTION_L2_128B, CU_TENSOR_MAP_FLOAT_OOB_FILL_NONE);
}

extern "C" void kernel_launch(void* const* d_in, const int* in_sizes, int n_in,
                              void* d_out, int out_size) {
    const float* x   = (const float*)d_in[0];
    const float* wq  = (const float*)d_in[1];
    const float* wk  = (const float*)d_in[2];
    const float* wv  = (const float*)d_in[3];
    const float* wg  = (const float*)d_in[4];
    const float* wo  = (const float*)d_in[5];
    const float* lnw = (const float*)d_in[6];
    const float* lnb = (const float*)d_in[7];
    float* out = (float*)d_out;

    float *G;
    __nv_bfloat16 *xhi, *xlo, *ahi, *alo;
    __nv_bfloat16 *whi[5], *wlo[5];
    __nv_bfloat16 *qhi, *qlo, *khi, *klo, *vhi, *vlo;
    cudaGetSymbolAddress((void**)&G, g_G);
    cudaGetSymbolAddress((void**)&xhi, g_xhi);  cudaGetSymbolAddress((void**)&xlo, g_xlo);
    cudaGetSymbolAddress((void**)&ahi, g_ahi);  cudaGetSymbolAddress((void**)&alo, g_alo);
    cudaGetSymbolAddress((void**)&whi[0], g_wqhi); cudaGetSymbolAddress((void**)&wlo[0], g_wqlo);
    cudaGetSymbolAddress((void**)&whi[1], g_wkhi); cudaGetSymbolAddress((void**)&wlo[1], g_wklo);
    cudaGetSymbolAddress((void**)&whi[2], g_wvhi); cudaGetSymbolAddress((void**)&wlo[2], g_wvlo);
    cudaGetSymbolAddress((void**)&whi[3], g_wghi); cudaGetSymbolAddress((void**)&wlo[3], g_wglo);
    cudaGetSymbolAddress((void**)&whi[4], g_wohi); cudaGetSymbolAddress((void**)&wlo[4], g_wolo);
    cudaGetSymbolAddress((void**)&qhi, g_Qhi); cudaGetSymbolAddress((void**)&qlo, g_Qlo);
    cudaGetSymbolAddress((void**)&khi, g_Khi); cudaGetSymbolAddress((void**)&klo, g_Klo);
    cudaGetSymbolAddress((void**)&vhi, g_Vhi); cudaGetSymbolAddress((void**)&vlo, g_Vlo);

    static CUtensorMap h_maps[14];
    void* encPtr = nullptr;
    cudaDriverEntryPointQueryResult qres;
    cudaGetDriverEntryPoint("cuTensorMapEncodeTiled", &encPtr, cudaEnableDefault, &qres);
    EncodeFn enc = (EncodeFn)encPtr;
    make_map2d(enc, &h_maps[0], xhi, 128);
    make_map2d(enc, &h_maps[1], xlo, 128);
    make_map2d(enc, &h_maps[2], ahi, 128);
    make_map2d(enc, &h_maps[3], alo, 128);
    for (int p = 0; p < 5; p++) {
        make_map2d(enc, &h_maps[4 + 2 * p],     whi[p], 256);
        make_map2d(enc, &h_maps[4 + 2 * p + 1], wlo[p], 256);
    }
    cudaMemcpyToSymbolAsync(g_tmaps, h_maps, sizeof(h_maps), 0, cudaMemcpyHostToDevice, 0);
    CUtensorMap* tm;
    cudaGetSymbolAddress((void**)&tm, g_tmaps);

    cudaFuncSetAttribute(gemm3, cudaFuncAttributeMaxDynamicSharedMemorySize, GEMM_SMEM);
    cudaFuncSetAttribute(retention_tc, cudaFuncAttributeMaxDynamicSharedMemorySize, AT_SMEM);

    cvt6<<<dim3(1024, 6), 256>>>(x,  xhi,    xlo,
                                 wq, whi[0], wlo[0],
                                 wk, whi[1], wlo[1],
                                 wv, whi[2], wlo[2],
                                 wg, whi[3], wlo[3],
                                 wo, whi[4], wlo[4]);

    dim3 gg(DIM / GBN, SEQ / GBM);
    gemm3<<<gg, GTHREADS, GEMM_SMEM>>>(tm + 0, tm + 1, tm + 4,  tm + 5,  nullptr, qhi, qlo, 1);
    gemm3<<<gg, GTHREADS, GEMM_SMEM>>>(tm + 0, tm + 1, tm + 6,  tm + 7,  nullptr, khi, klo, 1);
    gemm3<<<gg, GTHREADS, GEMM_SMEM>>>(tm + 0, tm + 1, tm + 8,  tm + 9,  nullptr, vhi, vlo, 1);
    gemm3<<<gg, GTHREADS, GEMM_SMEM>>>(tm + 0, tm + 1, tm + 10, tm + 11, G, nullptr, nullptr, 0);

    retention_tc<<<dim3(SEQ / 128, NH), 512, AT_SMEM>>>();

    ln_silu_gate<<<SEQ, 256>>>(lnw, lnb, ahi, alo);

    gemm3<<<gg, GTHREADS, GEMM_SMEM>>>(tm + 2, tm + 3, tm + 12, tm + 13, out, nullptr, nullptr, 0);
}

// round 14
// speedup vs baseline: 1.0689x; 1.0689x over previous
#include <cuda_runtime.h>
#include <cuda.h>
#include <cuda_bf16.h>
#include <math.h>
#include <cstdint>
#include <cstring>

#define SEQ 2048
#define DIM 2048
#define NH 16
#define HDIM 128

// ------------------------- scratch (device globals) -------------------------
__device__ float g_G[SEQ * DIM];
__device__ float g_Y[SEQ * DIM];

__device__ __nv_bfloat16 g_xhi[SEQ * DIM],  g_xlo[SEQ * DIM];
__device__ __nv_bfloat16 g_wqhi[DIM * DIM], g_wqlo[DIM * DIM];
__device__ __nv_bfloat16 g_wkhi[DIM * DIM], g_wklo[DIM * DIM];
__device__ __nv_bfloat16 g_wvhi[DIM * DIM], g_wvlo[DIM * DIM];
__device__ __nv_bfloat16 g_wghi[DIM * DIM], g_wglo[DIM * DIM];
__device__ __nv_bfloat16 g_wohi[DIM * DIM], g_wolo[DIM * DIM];
__device__ __nv_bfloat16 g_Qhi[SEQ * DIM],  g_Qlo[SEQ * DIM];
__device__ __nv_bfloat16 g_Khi[SEQ * DIM],  g_Klo[SEQ * DIM];
__device__ __nv_bfloat16 g_Vhi[SEQ * DIM],  g_Vlo[SEQ * DIM];
__device__ __nv_bfloat16 g_ahi[SEQ * DIM],  g_alo[SEQ * DIM];

__device__ CUtensorMap g_tmaps[14];

// ------------------------- helpers -------------------------
__device__ __forceinline__ uint32_t smem_u32(const void* p) {
    uint32_t a;
    asm("{ .reg .u64 t; cvta.to.shared.u64 t, %1; cvt.u32.u64 %0, t; }" : "=r"(a) : "l"(p));
    return a;
}
__device__ __forceinline__ void cp16(uint32_t dst, const void* src) {
    asm volatile("cp.async.cg.shared.global [%0], [%1], 16;" :: "r"(dst), "l"(src));
}
__device__ __forceinline__ void ldx4(uint32_t* r, uint32_t addr) {
    asm volatile("ldmatrix.sync.aligned.m8n8.x4.shared.b16 {%0,%1,%2,%3}, [%4];"
                 : "=r"(r[0]), "=r"(r[1]), "=r"(r[2]), "=r"(r[3]) : "r"(addr));
}
__device__ __forceinline__ void ldx4t(uint32_t* r, uint32_t addr) {
    asm volatile("ldmatrix.sync.aligned.m8n8.x4.trans.shared.b16 {%0,%1,%2,%3}, [%4];"
                 : "=r"(r[0]), "=r"(r[1]), "=r"(r[2]), "=r"(r[3]) : "r"(addr));
}
__device__ __forceinline__ void mma16816(float* c, const uint32_t* a, uint32_t b0, uint32_t b1) {
    asm volatile(
        "mma.sync.aligned.m16n8k16.row.col.f32.bf16.bf16.f32 "
        "{%0,%1,%2,%3}, {%4,%5,%6,%7}, {%8,%9}, {%0,%1,%2,%3};"
        : "+f"(c[0]), "+f"(c[1]), "+f"(c[2]), "+f"(c[3])
        : "r"(a[0]), "r"(a[1]), "r"(a[2]), "r"(a[3]), "r"(b0), "r"(b1));
}

#define MBARRIER_INIT(addr, cnt) \
    asm volatile("mbarrier.init.shared.b64 [%0], %1;" :: "r"(addr), "r"(cnt) : "memory")
#define MBARRIER_ARRIVE(addr) \
    asm volatile("mbarrier.arrive.shared.b64 _, [%0];" :: "r"(addr) : "memory")
#define MBARRIER_EXPECT_TX(addr, bytes) \
    asm volatile("mbarrier.arrive.expect_tx.shared.b64 _, [%0], %1;" :: "r"(addr), "r"(bytes) : "memory")
#define MBARRIER_WAIT_PARITY(addr, par) do { \
    uint32_t _m = (addr); uint32_t _p = (par); uint32_t _d; \
    asm volatile("{ .reg .pred p; mbarrier.try_wait.parity.acquire.cta.shared::cta.b64 p, [%1], %2; selp.b32 %0,1,0,p; }" \
        : "=r"(_d) : "r"(_m), "r"(_p) : "memory"); \
    if (!_d) { \
        asm volatile("{ .reg .pred P1; WL_%=: mbarrier.try_wait.parity.acquire.cta.shared::cta.b64 P1, [%0], %1, 0x989680; @P1 bra.uni WD_%=; bra.uni WL_%=; WD_%=: }" \
            :: "r"(_m), "r"(_p) : "memory"); \
    } \
} while (0)
#define TMA_LOAD_2D(smem_addr, map, cx, cy, mbar) \
    asm volatile("cp.async.bulk.tensor.2d.shared::cta.global.tile.mbarrier::complete_tx::bytes " \
                 "[%0], [%1, {%2, %3}], [%4];" \
                 :: "r"(smem_addr), "l"(map), "r"(cx), "r"(cy), "r"(mbar) : "memory")

// ---------------------------------------------------------------------------
// Fused 3-pass hi/lo bf16 GEMM (TN). Tile 128x256, BK=64, 512 threads (4x4).
// TMA + full/empty mbarrier ring (R11 scheme). Inner loop splits B into two
// halves to cut register pressure below the 128/thread cap (no spills).
// ---------------------------------------------------------------------------
static constexpr int GBM = 128, GBN = 256, GBK = 64;
static constexpr int GTHREADS = 512;
static constexpr int NCH = DIM / GBK;
static constexpr int OF_AH = 0;
static constexpr int OF_AL = 16384;
static constexpr int OF_BH = 32768;
static constexpr int OF_BL = 65536;
static constexpr int GBUF = 98304;
static constexpr int GEMM_SMEM = 2 * GBUF + 64;

__device__ __forceinline__ void tma_chunk(uint32_t buf, const CUtensorMap* mAh,
                                          const CUtensorMap* mAl, const CUtensorMap* mBh,
                                          const CUtensorMap* mBl, int m0, int n0, int kc,
                                          uint32_t bar) {
    MBARRIER_EXPECT_TX(bar, (uint32_t)GBUF);
    TMA_LOAD_2D(buf + OF_AH, mAh, kc, m0, bar);
    TMA_LOAD_2D(buf + OF_AL, mAl, kc, m0, bar);
    TMA_LOAD_2D(buf + OF_BH, mBh, kc, n0, bar);
    TMA_LOAD_2D(buf + OF_BL, mBl, kc, n0, bar);
}

__global__ __launch_bounds__(GTHREADS, 1) void gemm3(const CUtensorMap* __restrict__ mAh,
                                                     const CUtensorMap* __restrict__ mAl,
                                                     const CUtensorMap* __restrict__ mBh,
                                                     const CUtensorMap* __restrict__ mBl,
                                                     float* __restrict__ C,
                                                     __nv_bfloat16* __restrict__ Chi,
                                                     __nv_bfloat16* __restrict__ Clo,
                                                     int mode) {
    extern __shared__ char smem[];
    uint32_t sb = smem_u32(smem);
    uint32_t full0 = sb + 2 * GBUF, full1 = full0 + 8;
    uint32_t empty0 = full1 + 8, empty1 = empty0 + 8;
    int tid = threadIdx.x;
    int wid = tid >> 5, lane = tid & 31;
    int wm = wid & 3, wn = wid >> 2;
    int m0 = blockIdx.y * GBM, n0 = blockIdx.x * GBN;

    if (tid == 0) {
        asm volatile("prefetch.tensormap [%0];" :: "l"(mAh));
        asm volatile("prefetch.tensormap [%0];" :: "l"(mAl));
        asm volatile("prefetch.tensormap [%0];" :: "l"(mBh));
        asm volatile("prefetch.tensormap [%0];" :: "l"(mBl));
        MBARRIER_INIT(full0, 1);
        MBARRIER_INIT(full1, 1);
        MBARRIER_INIT(empty0, GTHREADS);
        MBARRIER_INIT(empty1, GTHREADS);
    }
    __syncthreads();
    if (tid == 0) {
        tma_chunk(sb, mAh, mAl, mBh, mBl, m0, n0, 0, full0);
        tma_chunk(sb + GBUF, mAh, mAl, mBh, mBl, m0, n0, GBK, full1);
    }

    int a_mh = (lane >> 3) & 1, a_kh = lane >> 4, lr = lane & 7;
    uint32_t aOff[2]; int aR7[2];
#pragma unroll
    for (int i = 0; i < 2; i++) {
        int row = wm * 32 + i * 16 + a_mh * 8 + lr;
        aOff[i] = row * 128; aR7[i] = row & 7;
    }
    int b_jl = lane >> 4, b_kh = (lane >> 3) & 1;
    uint32_t bOff[4]; int bR7[4];
#pragma unroll
    for (int p = 0; p < 4; p++) {
        int row = wn * 64 + p * 16 + b_jl * 8 + lr;
        bOff[p] = row * 128; bR7[p] = row & 7;
    }

    float acc[2][8][4];
#pragma unroll
    for (int i = 0; i < 2; i++)
#pragma unroll
        for (int j = 0; j < 8; j++)
#pragma unroll
            for (int q = 0; q < 4; q++) acc[i][j][q] = 0.f;

    for (int t = 0; t < NCH; t++) {
        uint32_t full  = (t & 1) ? full1 : full0;
        uint32_t empty = (t & 1) ? empty1 : empty0;
        MBARRIER_WAIT_PARITY(full, (t >> 1) & 1);

        uint32_t buf = sb + (t & 1) * GBUF;
#pragma unroll
        for (int ks = 0; ks < 4; ks++) {
            int ca = ks * 2 + a_kh;
            int cb = ks * 2 + b_kh;
            uint32_t ah[2][4], al[2][4];
#pragma unroll
            for (int i = 0; i < 2; i++) {
                ldx4(ah[i], buf + OF_AH + aOff[i] + (((uint32_t)(ca ^ aR7[i])) << 4));
                ldx4(al[i], buf + OF_AL + aOff[i] + (((uint32_t)(ca ^ aR7[i])) << 4));
            }
            // process B in two halves to keep register pressure < 128/thread
#pragma unroll
            for (int ph = 0; ph < 2; ph++) {
                uint32_t bh[2][4], bl[2][4];
#pragma unroll
                for (int p2 = 0; p2 < 2; p2++) {
                    int p = ph * 2 + p2;
                    ldx4(bh[p2], buf + OF_BH + bOff[p] + (((uint32_t)(cb ^ bR7[p])) << 4));
                    ldx4(bl[p2], buf + OF_BL + bOff[p] + (((uint32_t)(cb ^ bR7[p])) << 4));
                }
#pragma unroll
                for (int i = 0; i < 2; i++)
#pragma unroll
                    for (int j4 = 0; j4 < 4; j4++) {
                        int j = ph * 4 + j4;
                        int p2 = j4 >> 1, jl = j4 & 1;
                        mma16816(acc[i][j], ah[i], bh[p2][2 * jl], bh[p2][2 * jl + 1]);
                        mma16816(acc[i][j], ah[i], bl[p2][2 * jl], bl[p2][2 * jl + 1]);
                        mma16816(acc[i][j], al[i], bh[p2][2 * jl], bh[p2][2 * jl + 1]);
                    }
            }
        }

        MBARRIER_ARRIVE(empty);                      // all threads signal consume
        if (t + 2 < NCH && tid == 0) {
            MBARRIER_WAIT_PARITY(empty, (t >> 1) & 1);
            tma_chunk(buf, mAh, mAl, mBh, mBl, m0, n0, (t + 2) * GBK, full);
        }
    }

    int qr = lane >> 2, qc = (lane & 3) * 2;
#pragma unroll
    for (int i = 0; i < 2; i++) {
        int mrow = m0 + wm * 32 + i * 16 + qr;
#pragma unroll
        for (int j = 0; j < 8; j++) {
            size_t base = (size_t)mrow * DIM + n0 + wn * 64 + j * 8 + qc;
            if (mode == 0) {
                C[base]               = acc[i][j][0];
                C[base + 1]           = acc[i][j][1];
                C[base + 8 * DIM]     = acc[i][j][2];
                C[base + 8 * DIM + 1] = acc[i][j][3];
            } else {
#pragma unroll
                for (int h2 = 0; h2 < 2; h2++) {
                    float v0 = acc[i][j][h2 * 2], v1 = acc[i][j][h2 * 2 + 1];
                    __nv_bfloat16 h0 = __float2bfloat16(v0), h1 = __float2bfloat16(v1);
                    __nv_bfloat16 l0 = __float2bfloat16(v0 - __bfloat162float(h0));
                    __nv_bfloat16 l1 = __float2bfloat16(v1 - __bfloat162float(h1));
                    size_t bb = base + h2 * 8 * DIM;
                    *(__nv_bfloat162*)(Chi + bb) = __nv_bfloat162(h0, h1);
                    *(__nv_bfloat162*)(Clo + bb) = __nv_bfloat162(l0, l1);
                }
            }
        }
    }
}

// ---------------------------------------------------------------------------
// fp32 -> bf16 hi/lo, all 6 tensors in one launch
// ---------------------------------------------------------------------------
__global__ __launch_bounds__(256) void cvt6(
    const float* s0, __nv_bfloat16* h0, __nv_bfloat16* l0,
    const float* s1, __nv_bfloat16* h1, __nv_bfloat16* l1,
    const float* s2, __nv_bfloat16* h2, __nv_bfloat16* l2,
    const float* s3, __nv_bfloat16* h3, __nv_bfloat16* l3,
    const float* s4, __nv_bfloat16* h4, __nv_bfloat16* l4,
    const float* s5, __nv_bfloat16* h5, __nv_bfloat16* l5) {
    const float* s; __nv_bfloat16 *hi, *lo;
    switch (blockIdx.y) {
        case 0: s = s0; hi = h0; lo = l0; break;
        case 1: s = s1; hi = h1; lo = l1; break;
        case 2: s = s2; hi = h2; lo = l2; break;
        case 3: s = s3; hi = h3; lo = l3; break;
        case 4: s = s4; hi = h4; lo = l4; break;
        default: s = s5; hi = h5; lo = l5; break;
    }
    int base = blockIdx.x * 1024 + threadIdx.x;
    float4 v[4];
#pragma unroll
    for (int u = 0; u < 4; u++) v[u] = ((const float4*)s)[base + u * 256];
#pragma unroll
    for (int u = 0; u < 4; u++) {
        int i = base + u * 256;
        __nv_bfloat16 a0 = __float2bfloat16(v[u].x), a1 = __float2bfloat16(v[u].y);
        __nv_bfloat16 a2 = __float2bfloat16(v[u].z), a3 = __float2bfloat16(v[u].w);
        __nv_bfloat16 b0 = __float2bfloat16(v[u].x - __bfloat162float(a0));
        __nv_bfloat16 b1 = __float2bfloat16(v[u].y - __bfloat162float(a1));
        __nv_bfloat16 b2 = __float2bfloat16(v[u].z - __bfloat162float(a2));
        __nv_bfloat16 b3 = __float2bfloat16(v[u].w - __bfloat162float(a3));
        ((__nv_bfloat162*)hi)[2 * i]     = __nv_bfloat162(a0, a1);
        ((__nv_bfloat162*)hi)[2 * i + 1] = __nv_bfloat162(a2, a3);
        ((__nv_bfloat162*)lo)[2 * i]     = __nv_bfloat162(b0, b1);
        ((__nv_bfloat162*)lo)[2 * i + 1] = __nv_bfloat162(b2, b3);
    }
}

// ---------------------------------------------------------------------------
// Tensor-core retention attention (BI=BJ=64, 8 warps, K/V double-buffered).
// grid (32 i-tiles, 16 heads), 256 threads. (round-11 version — known good)
// ---------------------------------------------------------------------------
static constexpr int KVBUF = 65536;
static constexpr int OQH = 0, OQL = 16384;
static constexpr int OKV = 32768;
static constexpr int OKH = 0, OKL = 16384, OVH = 32768, OVL = 49152;
static constexpr int OSH = 163840, OSL = 172032;
static constexpr int AT_SMEM = 180224;

__device__ __forceinline__ void at_load_kv(uint32_t kvbase,
                                           const __nv_bfloat16* Khg, const __nv_bfloat16* Klg,
                                           const __nv_bfloat16* Vhg, const __nv_bfloat16* Vlg,
                                           int j0, int tid) {
#pragma unroll
    for (int l = 0; l < 8; l++) {
        int idx = tid + l * 256;
        int arr = idx >> 10, ct = (idx >> 9) & 1, r = (idx >> 3) & 63, c = idx & 7;
        const __nv_bfloat16* src = (arr ? Klg : Khg) + (size_t)(j0 + r) * DIM + ct * 64 + c * 8;
        uint32_t dst = kvbase + (arr ? OKL : OKH) + ct * 8192 + r * 128 + (((c ^ (r & 7))) << 4);
        cp16(dst, src);
    }
#pragma unroll
    for (int l = 0; l < 8; l++) {
        int idx = tid + l * 256;
        int arr = idx >> 10, r = (idx >> 4) & 63, dc = idx & 15;
        const __nv_bfloat16* src = (arr ? Vlg : Vhg) + (size_t)(j0 + r) * DIM + dc * 8;
        uint32_t dst = kvbase + (arr ? OVL : OVH) + r * 256 + (((dc ^ (r & 7))) << 4);
        cp16(dst, src);
    }
}

__global__ __launch_bounds__(256, 1) void retention_tc() {
    extern __shared__ char smem[];
    uint32_t sb = smem_u32(smem);

    int head = blockIdx.y;
    int it = gridDim.x - 1 - blockIdx.x;
    int i0 = it * 64;
    int tid = threadIdx.x, lane = tid & 31, wid = tid >> 5;
    int wm = wid & 1, wn = wid >> 1;

    const float lg0 = -3.4657359027997265f;
    const float lg1 = -6.2383246250395075f;
    float gamma = 1.0f - expf(lg0 + (lg1 - lg0) * ((float)head * (1.0f / 15.0f)));
    float log2g = log2f(gamma);
    const float scale = 0.088388347648318447f;

    const __nv_bfloat16* Qhg = g_Qhi + head * HDIM;
    const __nv_bfloat16* Qlg = g_Qlo + head * HDIM;
    const __nv_bfloat16* Khg = g_Khi + head * HDIM;
    const __nv_bfloat16* Klg = g_Klo + head * HDIM;
    const __nv_bfloat16* Vhg = g_Vhi + head * HDIM;
    const __nv_bfloat16* Vlg = g_Vlo + head * HDIM;

    int qr = lane >> 2, qc = (lane & 3) * 2;
    int a_mh = (lane >> 3) & 1, a_kh = lane >> 4, lr = lane & 7;
    int b_jl = lane >> 4, b_kh = (lane >> 3) & 1;
    int v_m = (lane >> 3) & 1, v_g = lane >> 4;

    uint32_t aOff[2]; int aR7[2];
#pragma unroll
    for (int i = 0; i < 2; i++) {
        int row = wm * 32 + i * 16 + a_mh * 8 + lr;
        aOff[i] = row * 128; aR7[i] = row & 7;
    }
    int brow = wn * 16 + b_jl * 8 + lr;
    uint32_t bOff = brow * 128; int bR7 = brow & 7;

    float colfac[2][2];
#pragma unroll
    for (int jf = 0; jf < 2; jf++)
#pragma unroll
        for (int lb = 0; lb < 2; lb++) {
            int dj = wn * 16 + jf * 8 + qc + lb;
            colfac[jf][lb] = exp2f(-log2g * (float)dj) * scale;
        }

#pragma unroll
    for (int l = 0; l < 8; l++) {
        int idx = tid + l * 256;
        int arr = idx >> 10, ct = (idx >> 9) & 1, r = (idx >> 3) & 63, c = idx & 7;
        const __nv_bfloat16* src = (arr ? Qlg : Qhg) + (size_t)(i0 + r) * DIM + ct * 64 + c * 8;
        uint32_t dst = sb + (arr ? OQL : OQH) + ct * 8192 + r * 128 + (((c ^ (r & 7))) << 4);
        cp16(dst, src);
    }
    at_load_kv(sb + OKV, Khg, Klg, Vhg, Vlg, 0, tid);
    asm volatile("cp.async.commit_group;" ::: "memory");

    float yacc[2][4][4];
#pragma unroll
    for (int i = 0; i < 2; i++)
#pragma unroll
        for (int t = 0; t < 4; t++)
#pragma unroll
            for (int q = 0; q < 4; q++) yacc[i][t][q] = 0.f;

    for (int jt = 0; jt <= it; jt++) {
        int j0 = jt * 64;
        uint32_t kvb = sb + OKV + (jt & 1) * KVBUF;

        asm volatile("cp.async.wait_group 0;" ::: "memory");
        __syncthreads();

        if (jt < it) {
            at_load_kv(sb + OKV + ((jt + 1) & 1) * KVBUF, Khg, Klg, Vhg, Vlg, j0 + 64, tid);
            asm volatile("cp.async.commit_group;" ::: "memory");
        }

        float acc1[2][2][4];
#pragma unroll
        for (int i = 0; i < 2; i++)
#pragma unroll
            for (int j = 0; j < 2; j++)
#pragma unroll
                for (int q = 0; q < 4; q++) acc1[i][j][q] = 0.f;

#pragma unroll
        for (int ct = 0; ct < 2; ct++) {
#pragma unroll
            for (int ks = 0; ks < 4; ks++) {
                int ca = ks * 2 + a_kh;
                int cb = ks * 2 + b_kh;
                uint32_t qh[2][4], ql[2][4], bh[4], bl[4];
#pragma unroll
                for (int i = 0; i < 2; i++) {
                    ldx4(qh[i], sb + OQH + ct * 8192 + aOff[i] + (((uint32_t)(ca ^ aR7[i])) << 4));
                    ldx4(ql[i], sb + OQL + ct * 8192 + aOff[i] + (((uint32_t)(ca ^ aR7[i])) << 4));
                }
                ldx4(bh, kvb + OKH + ct * 8192 + bOff + (((uint32_t)(cb ^ bR7)) << 4));
                ldx4(bl, kvb + OKL + ct * 8192 + bOff + (((uint32_t)(cb ^ bR7)) << 4));
#pragma unroll
                for (int i = 0; i < 2; i++)
#pragma unroll
                    for (int j = 0; j < 2; j++) {
                        mma16816(acc1[i][j], qh[i], bh[2 * j], bh[2 * j + 1]);
                        mma16816(acc1[i][j], qh[i], bl[2 * j], bl[2 * j + 1]);
                        mma16816(acc1[i][j], ql[i], bh[2 * j], bh[2 * j + 1]);
                    }
            }
        }

        float rowfac[2][2];
#pragma unroll
        for (int i = 0; i < 2; i++)
#pragma unroll
            for (int h = 0; h < 2; h++) {
                int rrel = i0 - j0 + wm * 32 + i * 16 + qr + h * 8;
                rowfac[i][h] = exp2f(log2g * (float)rrel);
            }
#pragma unroll
        for (int i = 0; i < 2; i++)
#pragma unroll
            for (int j = 0; j < 2; j++)
#pragma unroll
                for (int h = 0; h < 2; h++) {
                    int row = wm * 32 + i * 16 + qr + h * 8;
                    int col = wn * 16 + j * 8 + qc;
                    int diff0 = (i0 + row) - (j0 + col);
                    float v0 = (diff0 >= 0) ? acc1[i][j][h * 2 + 0] * rowfac[i][h] * colfac[j][0] : 0.f;
                    float v1 = (diff0 >= 1) ? acc1[i][j][h * 2 + 1] * rowfac[i][h] * colfac[j][1] : 0.f;
                    __nv_bfloat16 h0 = __float2bfloat16(v0), h1 = __float2bfloat16(v1);
                    __nv_bfloat16 l0 = __float2bfloat16(v0 - __bfloat162float(h0));
                    __nv_bfloat16 l1 = __float2bfloat16(v1 - __bfloat162float(h1));
                    uint32_t off = row * 128 + ((((col >> 3) ^ (row & 7))) << 4) + (col & 7) * 2;
                    *(__nv_bfloat162*)(smem + OSH + off) = __nv_bfloat162(h0, h1);
                    *(__nv_bfloat162*)(smem + OSL + off) = __nv_bfloat162(l0, l1);
                }
        __syncthreads();

#pragma unroll
        for (int ks = 0; ks < 4; ks++) {
            int ca = ks * 2 + a_kh;
            uint32_t sh[2][4], sl[2][4], vh[2][4], vl[2][4];
#pragma unroll
            for (int i = 0; i < 2; i++) {
                ldx4(sh[i], sb + OSH + aOff[i] + (((uint32_t)(ca ^ aR7[i])) << 4));
                ldx4(sl[i], sb + OSL + aOff[i] + (((uint32_t)(ca ^ aR7[i])) << 4));
            }
            int vrow = ks * 16 + v_m * 8 + lr;
#pragma unroll
            for (int g = 0; g < 2; g++) {
                int dc = wn * 4 + g * 2 + v_g;
                uint32_t vo = vrow * 256 + (((uint32_t)(dc ^ (vrow & 7))) << 4);
                ldx4t(vh[g], kvb + OVH + vo);
                ldx4t(vl[g], kvb + OVL + vo);
            }
#pragma unroll
            for (int i = 0; i < 2; i++)
#pragma unroll
                for (int t = 0; t < 4; t++) {
                    int g = t >> 1, s2 = (t & 1) * 2;
                    mma16816(yacc[i][t], sh[i], vh[g][s2], vh[g][s2 + 1]);
                    mma16816(yacc[i][t], sh[i], vl[g][s2], vl[g][s2 + 1]);
                    mma16816(yacc[i][t], sl[i], vh[g][s2], vh[g][s2 + 1]);
                }
        }
    }

#pragma unroll
    for (int i = 0; i < 2; i++) {
        int row = i0 + wm * 32 + i * 16 + qr;
#pragma unroll
        for (int t = 0; t < 4; t++) {
            float* yp = g_Y + (size_t)row * DIM + head * HDIM + wn * 32 + t * 8 + qc;
            *(float2*)yp = make_float2(yacc[i][t][0], yacc[i][t][1]);
            *(float2*)(yp + 8 * DIM) = make_float2(yacc[i][t][2], yacc[i][t][3]);
        }
    }
}

// ---------------------------------------------------------------------------
// LayerNorm(Y) * silu(G) -> bf16 hi + lo arrays
// ---------------------------------------------------------------------------
__global__ __launch_bounds__(256) void ln_silu_gate(const float* __restrict__ lnw,
                                                    const float* __restrict__ lnb,
                                                    __nv_bfloat16* __restrict__ ohi,
                                                    __nv_bfloat16* __restrict__ olo) {
    int row = blockIdx.x;
    const float* y = g_Y + (size_t)row * DIM;
    const float* g = g_G + (size_t)row * DIM;
    int tid = threadIdx.x;

    float vals[8];
    float s = 0.f, ss = 0.f;
#pragma unroll
    for (int i = 0; i < 2; i++) {
        float4 v = *(const float4*)(y + tid * 4 + i * 1024);
        vals[i * 4 + 0] = v.x; vals[i * 4 + 1] = v.y;
        vals[i * 4 + 2] = v.z; vals[i * 4 + 3] = v.w;
        s += v.x + v.y + v.z + v.w;
        ss += v.x * v.x + v.y * v.y + v.z * v.z + v.w * v.w;
    }
#pragma unroll
    for (int off = 16; off > 0; off >>= 1) {
        s += __shfl_xor_sync(0xFFFFFFFFu, s, off);
        ss += __shfl_xor_sync(0xFFFFFFFFu, ss, off);
    }
    __shared__ float rs[8], rss[8];
    if ((tid & 31) == 0) { rs[tid >> 5] = s; rss[tid >> 5] = ss; }
    __syncthreads();
    s = 0.f; ss = 0.f;
#pragma unroll
    for (int i = 0; i < 8; i++) { s += rs[i]; ss += rss[i]; }

    float mu = s * (1.0f / DIM);
    float var = ss * (1.0f / DIM) - mu * mu;
    float rstd = rsqrtf(var + 1e-5f);

#pragma unroll
    for (int i = 0; i < 2; i++) {
        int c0 = tid * 4 + i * 1024;
        float4 gv = *(const float4*)(g + c0);
        float4 wv = *(const float4*)(lnw + c0);
        float4 bv = *(const float4*)(lnb + c0);
        float o[4];
        o[0] = ((vals[i * 4 + 0] - mu) * rstd * wv.x + bv.x) * (gv.x / (1.0f + expf(-gv.x)));
        o[1] = ((vals[i * 4 + 1] - mu) * rstd * wv.y + bv.y) * (gv.y / (1.0f + expf(-gv.y)));
        o[2] = ((vals[i * 4 + 2] - mu) * rstd * wv.z + bv.z) * (gv.z / (1.0f + expf(-gv.z)));
        o[3] = ((vals[i * 4 + 3] - mu) * rstd * wv.w + bv.w) * (gv.w / (1.0f + expf(-gv.w)));
        __nv_bfloat16 h[4], l[4];
#pragma unroll
        for (int j = 0; j < 4; j++) {
            h[j] = __float2bfloat16(o[j]);
            l[j] = __float2bfloat16(o[j] - __bfloat162float(h[j]));
        }
        size_t base = (size_t)row * DIM + c0;
        *(__nv_bfloat162*)(ohi + base)     = __nv_bfloat162(h[0], h[1]);
        *(__nv_bfloat162*)(ohi + base + 2) = __nv_bfloat162(h[2], h[3]);
        *(__nv_bfloat162*)(olo + base)     = __nv_bfloat162(l[0], l[1]);
        *(__nv_bfloat162*)(olo + base + 2) = __nv_bfloat162(l[2], l[3]);
    }
}

// ---------------------------------------------------------------------------
typedef CUresult (*EncodeFn)(CUtensorMap*, CUtensorMapDataType, cuuint32_t, void*,
                             const cuuint64_t*, const cuuint64_t*, const cuuint32_t*,
                             const cuuint32_t*, CUtensorMapInterleave, CUtensorMapSwizzle,
                             CUtensorMapL2promotion, CUtensorMapFloatOOBfill);

static void make_map2d(EncodeFn enc, CUtensorMap* m, void* ptr, uint32_t box_rows) {
    cuuint64_t dims[2] = {DIM, SEQ};
    cuuint64_t strides[1] = {DIM * 2};
    cuuint32_t box[2] = {64, box_rows};
    cuuint32_t es[2] = {1, 1};
    enc(m, CU_TENSOR_MAP_DATA_TYPE_BFLOAT16, 2, ptr, dims, strides, box, es,
        CU_TENSOR_MAP_INTERLEAVE_NONE, CU_TENSOR_MAP_SWIZZLE_128B,
        CU_TENSOR_MAP_L2_PROMOTION_L2_128B, CU_TENSOR_MAP_FLOAT_OOB_FILL_NONE);
}

extern "C" void kernel_launch(void* const* d_in, const int* in_sizes, int n_in,
                              void* d_out, int out_size) {
    const float* x   = (const float*)d_in[0];
    const float* wq  = (const float*)d_in[1];
    const float* wk  = (const float*)d_in[2];
    const float* wv  = (const float*)d_in[3];
    const float* wg  = (const float*)d_in[4];
    const float* wo  = (const float*)d_in[5];
    const float* lnw = (const float*)d_in[6];
    const float* lnb = (const float*)d_in[7];
    float* out = (float*)d_out;

    float *G;
    __nv_bfloat16 *xhi, *xlo, *ahi, *alo;
    __nv_bfloat16 *whi[5], *wlo[5];
    __nv_bfloat16 *qhi, *qlo, *khi, *klo, *vhi, *vlo;
    cudaGetSymbolAddress((void**)&G, g_G);
    cudaGetSymbolAddress((void**)&xhi, g_xhi);  cudaGetSymbolAddress((void**)&xlo, g_xlo);
    cudaGetSymbolAddress((void**)&ahi, g_ahi);  cudaGetSymbolAddress((void**)&alo, g_alo);
    cudaGetSymbolAddress((void**)&whi[0], g_wqhi); cudaGetSymbolAddress((void**)&wlo[0], g_wqlo);
    cudaGetSymbolAddress((void**)&whi[1], g_wkhi); cudaGetSymbolAddress((void**)&wlo[1], g_wklo);
    cudaGetSymbolAddress((void**)&whi[2], g_wvhi); cudaGetSymbolAddress((void**)&wlo[2], g_wvlo);
    cudaGetSymbolAddress((void**)&whi[3], g_wghi); cudaGetSymbolAddress((void**)&wlo[3], g_wglo);
    cudaGetSymbolAddress((void**)&whi[4], g_wohi); cudaGetSymbolAddress((void**)&wlo[4], g_wolo);
    cudaGetSymbolAddress((void**)&qhi, g_Qhi); cudaGetSymbolAddress((void**)&qlo, g_Qlo);
    cudaGetSymbolAddress((void**)&khi, g_Khi); cudaGetSymbolAddress((void**)&klo, g_Klo);
    cudaGetSymbolAddress((void**)&vhi, g_Vhi); cudaGetSymbolAddress((void**)&vlo, g_Vlo);

    static CUtensorMap h_maps[14];
    void* encPtr = nullptr;
    cudaDriverEntryPointQueryResult qres;
    cudaGetDriverEntryPoint("cuTensorMapEncodeTiled", &encPtr, cudaEnableDefault, &qres);
    EncodeFn enc = (EncodeFn)encPtr;
    make_map2d(enc, &h_maps[0], xhi, 128);
    make_map2d(enc, &h_maps[1], xlo, 128);
    make_map2d(enc, &h_maps[2], ahi, 128);
    make_map2d(enc, &h_maps[3], alo, 128);
    for (int p = 0; p < 5; p++) {
        make_map2d(enc, &h_maps[4 + 2 * p],     whi[p], 256);
        make_map2d(enc, &h_maps[4 + 2 * p + 1], wlo[p], 256);
    }
    cudaMemcpyToSymbolAsync(g_tmaps, h_maps, sizeof(h_maps), 0, cudaMemcpyHostToDevice, 0);
    CUtensorMap* tm;
    cudaGetSymbolAddress((void**)&tm, g_tmaps);

    cudaFuncSetAttribute(gemm3, cudaFuncAttributeMaxDynamicSharedMemorySize, GEMM_SMEM);
    cudaFuncSetAttribute(retention_tc, cudaFuncAttributeMaxDynamicSharedMemorySize, AT_SMEM);

    cvt6<<<dim3(1024, 6), 256>>>(x,  xhi,    xlo,
                                 wq, whi[0], wlo[0],
                                 wk, whi[1], wlo[1],
                                 wv, whi[2], wlo[2],
                                 wg, whi[3], wlo[3],
                                 wo, whi[4], wlo[4]);

    dim3 gg(DIM / GBN, SEQ / GBM);
    gemm3<<<gg, GTHREADS, GEMM_SMEM>>>(tm + 0, tm + 1, tm + 4,  tm + 5,  nullptr, qhi, qlo, 1);
    gemm3<<<gg, GTHREADS, GEMM_SMEM>>>(tm + 0, tm + 1, tm + 6,  tm + 7,  nullptr, khi, klo, 1);
    gemm3<<<gg, GTHREADS, GEMM_SMEM>>>(tm + 0, tm + 1, tm + 8,  tm + 9,  nullptr, vhi, vlo, 1);
    gemm3<<<gg, GTHREADS, GEMM_SMEM>>>(tm + 0, tm + 1, tm + 10, tm + 11, G, nullptr, nullptr, 0);

    retention_tc<<<dim3(SEQ / 64, NH), 256, AT_SMEM>>>();

    ln_silu_gate<<<SEQ, 256>>>(lnw, lnb, ahi, alo);

    gemm3<<<gg, GTHREADS, GEMM_SMEM>>>(tm + 2, tm + 3, tm + 12, tm + 13, out, nullptr, nullptr, 0);
}

// round 15
// speedup vs baseline: 1.0716x; 1.0026x over previous
#include <cuda_runtime.h>
#include <cuda.h>
#include <cuda_bf16.h>
#include <math.h>
#include <cstdint>
#include <cstring>

#define SEQ 2048
#define DIM 2048
#define NH 16
#define HDIM 128

// ------------------------- scratch (device globals) -------------------------
__device__ float g_G[SEQ * DIM];
__device__ float g_Y[SEQ * DIM];

__device__ __nv_bfloat16 g_xhi[SEQ * DIM],  g_xlo[SEQ * DIM];
__device__ __nv_bfloat16 g_wqhi[DIM * DIM], g_wqlo[DIM * DIM];
__device__ __nv_bfloat16 g_wkhi[DIM * DIM], g_wklo[DIM * DIM];
__device__ __nv_bfloat16 g_wvhi[DIM * DIM], g_wvlo[DIM * DIM];
__device__ __nv_bfloat16 g_wghi[DIM * DIM], g_wglo[DIM * DIM];
__device__ __nv_bfloat16 g_wohi[DIM * DIM], g_wolo[DIM * DIM];
__device__ __nv_bfloat16 g_Qhi[SEQ * DIM],  g_Qlo[SEQ * DIM];
__device__ __nv_bfloat16 g_Khi[SEQ * DIM],  g_Klo[SEQ * DIM];
__device__ __nv_bfloat16 g_Vhi[SEQ * DIM],  g_Vlo[SEQ * DIM];
__device__ __nv_bfloat16 g_ahi[SEQ * DIM],  g_alo[SEQ * DIM];

__device__ CUtensorMap g_tmaps[14];

// ------------------------- helpers -------------------------
__device__ __forceinline__ uint32_t smem_u32(const void* p) {
    uint32_t a;
    asm("{ .reg .u64 t; cvta.to.shared.u64 t, %1; cvt.u32.u64 %0, t; }" : "=r"(a) : "l"(p));
    return a;
}
__device__ __forceinline__ void cp16(uint32_t dst, const void* src) {
    asm volatile("cp.async.cg.shared.global [%0], [%1], 16;" :: "r"(dst), "l"(src));
}
__device__ __forceinline__ void ldx4(uint32_t* r, uint32_t addr) {
    asm volatile("ldmatrix.sync.aligned.m8n8.x4.shared.b16 {%0,%1,%2,%3}, [%4];"
                 : "=r"(r[0]), "=r"(r[1]), "=r"(r[2]), "=r"(r[3]) : "r"(addr));
}
__device__ __forceinline__ void ldx4t(uint32_t* r, uint32_t addr) {
    asm volatile("ldmatrix.sync.aligned.m8n8.x4.trans.shared.b16 {%0,%1,%2,%3}, [%4];"
                 : "=r"(r[0]), "=r"(r[1]), "=r"(r[2]), "=r"(r[3]) : "r"(addr));
}
__device__ __forceinline__ void mma16816(float* c, const uint32_t* a, uint32_t b0, uint32_t b1) {
    asm volatile(
        "mma.sync.aligned.m16n8k16.row.col.f32.bf16.bf16.f32 "
        "{%0,%1,%2,%3}, {%4,%5,%6,%7}, {%8,%9}, {%0,%1,%2,%3};"
        : "+f"(c[0]), "+f"(c[1]), "+f"(c[2]), "+f"(c[3])
        : "r"(a[0]), "r"(a[1]), "r"(a[2]), "r"(a[3]), "r"(b0), "r"(b1));
}

#define MBARRIER_INIT(addr, cnt) \
    asm volatile("mbarrier.init.shared.b64 [%0], %1;" :: "r"(addr), "r"(cnt) : "memory")
#define MBARRIER_ARRIVE(addr) \
    asm volatile("mbarrier.arrive.shared.b64 _, [%0];" :: "r"(addr) : "memory")
#define MBARRIER_EXPECT_TX(addr, bytes) \
    asm volatile("mbarrier.arrive.expect_tx.shared.b64 _, [%0], %1;" :: "r"(addr), "r"(bytes) : "memory")
#define MBARRIER_WAIT_PARITY(addr, par) do { \
    uint32_t _m = (addr); uint32_t _p = (par); uint32_t _d; \
    asm volatile("{ .reg .pred p; mbarrier.try_wait.parity.acquire.cta.shared::cta.b64 p, [%1], %2; selp.b32 %0,1,0,p; }" \
        : "=r"(_d) : "r"(_m), "r"(_p) : "memory"); \
    if (!_d) { \
        asm volatile("{ .reg .pred P1; WL_%=: mbarrier.try_wait.parity.acquire.cta.shared::cta.b64 P1, [%0], %1, 0x989680; @P1 bra.uni WD_%=; bra.uni WL_%=; WD_%=: }" \
            :: "r"(_m), "r"(_p) : "memory"); \
    } \
} while (0)
#define TMA_LOAD_2D(smem_addr, map, cx, cy, mbar) \
    asm volatile("cp.async.bulk.tensor.2d.shared::cta.global.tile.mbarrier::complete_tx::bytes " \
                 "[%0], [%1, {%2, %3}], [%4];" \
                 :: "r"(smem_addr), "l"(map), "r"(cx), "r"(cy), "r"(mbar) : "memory")

// ---------------------------------------------------------------------------
// Fused 3-pass hi/lo bf16 GEMM body (TN). Tile 128x256, BK=64, 512 thr (4x4).
// TMA + full/empty mbarrier ring. B processed in two halves (reg pressure).
// ---------------------------------------------------------------------------
static constexpr int GBM = 128, GBN = 256, GBK = 64;
static constexpr int GTHREADS = 512;
static constexpr int NCH = DIM / GBK;
static constexpr int OF_AH = 0;
static constexpr int OF_AL = 16384;
static constexpr int OF_BH = 32768;
static constexpr int OF_BL = 65536;
static constexpr int GBUF = 98304;
static constexpr int GEMM_SMEM = 2 * GBUF + 64;

__device__ __forceinline__ void tma_chunk(uint32_t buf, const CUtensorMap* mAh,
                                          const CUtensorMap* mAl, const CUtensorMap* mBh,
                                          const CUtensorMap* mBl, int m0, int n0, int kc,
                                          uint32_t bar) {
    MBARRIER_EXPECT_TX(bar, (uint32_t)GBUF);
    TMA_LOAD_2D(buf + OF_AH, mAh, kc, m0, bar);
    TMA_LOAD_2D(buf + OF_AL, mAl, kc, m0, bar);
    TMA_LOAD_2D(buf + OF_BH, mBh, kc, n0, bar);
    TMA_LOAD_2D(buf + OF_BL, mBl, kc, n0, bar);
}

__device__ __forceinline__ void gemm3_body(const CUtensorMap* mAh, const CUtensorMap* mAl,
                                           const CUtensorMap* mBh, const CUtensorMap* mBl,
                                           float* C, __nv_bfloat16* Chi, __nv_bfloat16* Clo,
                                           int mode, char* smem, int m0, int n0) {
    uint32_t sb = smem_u32(smem);
    uint32_t full0 = sb + 2 * GBUF, full1 = full0 + 8;
    uint32_t empty0 = full1 + 8, empty1 = empty0 + 8;
    int tid = threadIdx.x;
    int wid = tid >> 5, lane = tid & 31;
    int wm = wid & 3, wn = wid >> 2;

    if (tid == 0) {
        asm volatile("prefetch.tensormap [%0];" :: "l"(mAh));
        asm volatile("prefetch.tensormap [%0];" :: "l"(mAl));
        asm volatile("prefetch.tensormap [%0];" :: "l"(mBh));
        asm volatile("prefetch.tensormap [%0];" :: "l"(mBl));
        MBARRIER_INIT(full0, 1);
        MBARRIER_INIT(full1, 1);
        MBARRIER_INIT(empty0, GTHREADS);
        MBARRIER_INIT(empty1, GTHREADS);
    }
    __syncthreads();
    if (tid == 0) {
        tma_chunk(sb, mAh, mAl, mBh, mBl, m0, n0, 0, full0);
        tma_chunk(sb + GBUF, mAh, mAl, mBh, mBl, m0, n0, GBK, full1);
    }

    int a_mh = (lane >> 3) & 1, a_kh = lane >> 4, lr = lane & 7;
    uint32_t aOff[2]; int aR7[2];
#pragma unroll
    for (int i = 0; i < 2; i++) {
        int row = wm * 32 + i * 16 + a_mh * 8 + lr;
        aOff[i] = row * 128; aR7[i] = row & 7;
    }
    int b_jl = lane >> 4, b_kh = (lane >> 3) & 1;
    uint32_t bOff[4]; int bR7[4];
#pragma unroll
    for (int p = 0; p < 4; p++) {
        int row = wn * 64 + p * 16 + b_jl * 8 + lr;
        bOff[p] = row * 128; bR7[p] = row & 7;
    }

    float acc[2][8][4];
#pragma unroll
    for (int i = 0; i < 2; i++)
#pragma unroll
        for (int j = 0; j < 8; j++)
#pragma unroll
            for (int q = 0; q < 4; q++) acc[i][j][q] = 0.f;

    for (int t = 0; t < NCH; t++) {
        uint32_t full  = (t & 1) ? full1 : full0;
        uint32_t empty = (t & 1) ? empty1 : empty0;
        MBARRIER_WAIT_PARITY(full, (t >> 1) & 1);

        uint32_t buf = sb + (t & 1) * GBUF;
#pragma unroll
        for (int ks = 0; ks < 4; ks++) {
            int ca = ks * 2 + a_kh;
            int cb = ks * 2 + b_kh;
            uint32_t ah[2][4], al[2][4];
#pragma unroll
            for (int i = 0; i < 2; i++) {
                ldx4(ah[i], buf + OF_AH + aOff[i] + (((uint32_t)(ca ^ aR7[i])) << 4));
                ldx4(al[i], buf + OF_AL + aOff[i] + (((uint32_t)(ca ^ aR7[i])) << 4));
            }
#pragma unroll
            for (int ph = 0; ph < 2; ph++) {
                uint32_t bh[2][4], bl[2][4];
#pragma unroll
                for (int p2 = 0; p2 < 2; p2++) {
                    int p = ph * 2 + p2;
                    ldx4(bh[p2], buf + OF_BH + bOff[p] + (((uint32_t)(cb ^ bR7[p])) << 4));
                    ldx4(bl[p2], buf + OF_BL + bOff[p] + (((uint32_t)(cb ^ bR7[p])) << 4));
                }
#pragma unroll
                for (int i = 0; i < 2; i++)
#pragma unroll
                    for (int j4 = 0; j4 < 4; j4++) {
                        int j = ph * 4 + j4;
                        int p2 = j4 >> 1, jl = j4 & 1;
                        mma16816(acc[i][j], ah[i], bh[p2][2 * jl], bh[p2][2 * jl + 1]);
                        mma16816(acc[i][j], ah[i], bl[p2][2 * jl], bl[p2][2 * jl + 1]);
                        mma16816(acc[i][j], al[i], bh[p2][2 * jl], bh[p2][2 * jl + 1]);
                    }
            }
        }

        MBARRIER_ARRIVE(empty);
        if (t + 2 < NCH && tid == 0) {
            MBARRIER_WAIT_PARITY(empty, (t >> 1) & 1);
            tma_chunk(buf, mAh, mAl, mBh, mBl, m0, n0, (t + 2) * GBK, full);
        }
    }

    int qr = lane >> 2, qc = (lane & 3) * 2;
#pragma unroll
    for (int i = 0; i < 2; i++) {
        int mrow = m0 + wm * 32 + i * 16 + qr;
#pragma unroll
        for (int j = 0; j < 8; j++) {
            size_t base = (size_t)mrow * DIM + n0 + wn * 64 + j * 8 + qc;
            if (mode == 0) {
                C[base]               = acc[i][j][0];
                C[base + 1]           = acc[i][j][1];
                C[base + 8 * DIM]     = acc[i][j][2];
                C[base + 8 * DIM + 1] = acc[i][j][3];
            } else {
#pragma unroll
                for (int h2 = 0; h2 < 2; h2++) {
                    float v0 = acc[i][j][h2 * 2], v1 = acc[i][j][h2 * 2 + 1];
                    __nv_bfloat16 h0 = __float2bfloat16(v0), h1 = __float2bfloat16(v1);
                    __nv_bfloat16 l0 = __float2bfloat16(v0 - __bfloat162float(h0));
                    __nv_bfloat16 l1 = __float2bfloat16(v1 - __bfloat162float(h1));
                    size_t bb = base + h2 * 8 * DIM;
                    *(__nv_bfloat162*)(Chi + bb) = __nv_bfloat162(h0, h1);
                    *(__nv_bfloat162*)(Clo + bb) = __nv_bfloat162(l0, l1);
                }
            }
        }
    }
}

// final wo projection: single GEMM
__global__ __launch_bounds__(GTHREADS, 1) void gemm3(const CUtensorMap* __restrict__ mAh,
                                                     const CUtensorMap* __restrict__ mAl,
                                                     const CUtensorMap* __restrict__ mBh,
                                                     const CUtensorMap* __restrict__ mBl,
                                                     float* __restrict__ C) {
    extern __shared__ char smem[];
    gemm3_body(mAh, mAl, mBh, mBl, C, nullptr, nullptr, 0, smem,
               blockIdx.y * GBM, blockIdx.x * GBN);
}

// merged Q/K/V/G projections: grid (8, 16, 4), z selects weight/output.
// tmaps layout: [0]=xhi [1]=xlo [4..11]=wq/wk/wv/wg hi,lo pairs
__global__ __launch_bounds__(GTHREADS, 1) void gemm3x4(
    const CUtensorMap* __restrict__ tm,
    __nv_bfloat16* __restrict__ qhi, __nv_bfloat16* __restrict__ qlo,
    __nv_bfloat16* __restrict__ khi, __nv_bfloat16* __restrict__ klo,
    __nv_bfloat16* __restrict__ vhi, __nv_bfloat16* __restrict__ vlo,
    float* __restrict__ G) {
    extern __shared__ char smem[];
    int z = blockIdx.z;
    const CUtensorMap* mBh = tm + 4 + 2 * z;
    const CUtensorMap* mBl = tm + 5 + 2 * z;
    __nv_bfloat16 *Chi = nullptr, *Clo = nullptr;
    float* Cf = nullptr;
    int mode;
    if (z == 0)      { Chi = qhi; Clo = qlo; mode = 1; }
    else if (z == 1) { Chi = khi; Clo = klo; mode = 1; }
    else if (z == 2) { Chi = vhi; Clo = vlo; mode = 1; }
    else             { Cf = G;               mode = 0; }
    gemm3_body(tm + 0, tm + 1, mBh, mBl, Cf, Chi, Clo, mode, smem,
               blockIdx.y * GBM, blockIdx.x * GBN);
}

// ---------------------------------------------------------------------------
// fp32 -> bf16 hi/lo, all 6 tensors in one launch
// ---------------------------------------------------------------------------
__global__ __launch_bounds__(256) void cvt6(
    const float* s0, __nv_bfloat16* h0, __nv_bfloat16* l0,
    const float* s1, __nv_bfloat16* h1, __nv_bfloat16* l1,
    const float* s2, __nv_bfloat16* h2, __nv_bfloat16* l2,
    const float* s3, __nv_bfloat16* h3, __nv_bfloat16* l3,
    const float* s4, __nv_bfloat16* h4, __nv_bfloat16* l4,
    const float* s5, __nv_bfloat16* h5, __nv_bfloat16* l5) {
    const float* s; __nv_bfloat16 *hi, *lo;
    switch (blockIdx.y) {
        case 0: s = s0; hi = h0; lo = l0; break;
        case 1: s = s1; hi = h1; lo = l1; break;
        case 2: s = s2; hi = h2; lo = l2; break;
        case 3: s = s3; hi = h3; lo = l3; break;
        case 4: s = s4; hi = h4; lo = l4; break;
        default: s = s5; hi = h5; lo = l5; break;
    }
    int base = blockIdx.x * 1024 + threadIdx.x;
    float4 v[4];
#pragma unroll
    for (int u = 0; u < 4; u++) v[u] = ((const float4*)s)[base + u * 256];
#pragma unroll
    for (int u = 0; u < 4; u++) {
        int i = base + u * 256;
        __nv_bfloat16 a0 = __float2bfloat16(v[u].x), a1 = __float2bfloat16(v[u].y);
        __nv_bfloat16 a2 = __float2bfloat16(v[u].z), a3 = __float2bfloat16(v[u].w);
        __nv_bfloat16 b0 = __float2bfloat16(v[u].x - __bfloat162float(a0));
        __nv_bfloat16 b1 = __float2bfloat16(v[u].y - __bfloat162float(a1));
        __nv_bfloat16 b2 = __float2bfloat16(v[u].z - __bfloat162float(a2));
        __nv_bfloat16 b3 = __float2bfloat16(v[u].w - __bfloat162float(a3));
        ((__nv_bfloat162*)hi)[2 * i]     = __nv_bfloat162(a0, a1);
        ((__nv_bfloat162*)hi)[2 * i + 1] = __nv_bfloat162(a2, a3);
        ((__nv_bfloat162*)lo)[2 * i]     = __nv_bfloat162(b0, b1);
        ((__nv_bfloat162*)lo)[2 * i + 1] = __nv_bfloat162(b2, b3);
    }
}

// ---------------------------------------------------------------------------
// Tensor-core retention attention (BI=BJ=64, 8 warps, K/V double-buffered).
// grid (32 i-tiles, 16 heads), 256 threads. (round-11 version — known good)
// ---------------------------------------------------------------------------
static constexpr int KVBUF = 65536;
static constexpr int OQH = 0, OQL = 16384;
static constexpr int OKV = 32768;
static constexpr int OKH = 0, OKL = 16384, OVH = 32768, OVL = 49152;
static constexpr int OSH = 163840, OSL = 172032;
static constexpr int AT_SMEM = 180224;

__device__ __forceinline__ void at_load_kv(uint32_t kvbase,
                                           const __nv_bfloat16* Khg, const __nv_bfloat16* Klg,
                                           const __nv_bfloat16* Vhg, const __nv_bfloat16* Vlg,
                                           int j0, int tid) {
#pragma unroll
    for (int l = 0; l < 8; l++) {
        int idx = tid + l * 256;
        int arr = idx >> 10, ct = (idx >> 9) & 1, r = (idx >> 3) & 63, c = idx & 7;
        const __nv_bfloat16* src = (arr ? Klg : Khg) + (size_t)(j0 + r) * DIM + ct * 64 + c * 8;
        uint32_t dst = kvbase + (arr ? OKL : OKH) + ct * 8192 + r * 128 + (((c ^ (r & 7))) << 4);
        cp16(dst, src);
    }
#pragma unroll
    for (int l = 0; l < 8; l++) {
        int idx = tid + l * 256;
        int arr = idx >> 10, r = (idx >> 4) & 63, dc = idx & 15;
        const __nv_bfloat16* src = (arr ? Vlg : Vhg) + (size_t)(j0 + r) * DIM + dc * 8;
        uint32_t dst = kvbase + (arr ? OVL : OVH) + r * 256 + (((dc ^ (r & 7))) << 4);
        cp16(dst, src);
    }
}

__global__ __launch_bounds__(256, 1) void retention_tc() {
    extern __shared__ char smem[];
    uint32_t sb = smem_u32(smem);

    int head = blockIdx.y;
    int it = gridDim.x - 1 - blockIdx.x;
    int i0 = it * 64;
    int tid = threadIdx.x, lane = tid & 31, wid = tid >> 5;
    int wm = wid & 1, wn = wid >> 1;

    const float lg0 = -3.4657359027997265f;
    const float lg1 = -6.2383246250395075f;
    float gamma = 1.0f - expf(lg0 + (lg1 - lg0) * ((float)head * (1.0f / 15.0f)));
    float log2g = log2f(gamma);
    const float scale = 0.088388347648318447f;

    const __nv_bfloat16* Qhg = g_Qhi + head * HDIM;
    const __nv_bfloat16* Qlg = g_Qlo + head * HDIM;
    const __nv_bfloat16* Khg = g_Khi + head * HDIM;
    const __nv_bfloat16* Klg = g_Klo + head * HDIM;
    const __nv_bfloat16* Vhg = g_Vhi + head * HDIM;
    const __nv_bfloat16* Vlg = g_Vlo + head * HDIM;

    int qr = lane >> 2, qc = (lane & 3) * 2;
    int a_mh = (lane >> 3) & 1, a_kh = lane >> 4, lr = lane & 7;
    int b_jl = lane >> 4, b_kh = (lane >> 3) & 1;
    int v_m = (lane >> 3) & 1, v_g = lane >> 4;

    uint32_t aOff[2]; int aR7[2];
#pragma unroll
    for (int i = 0; i < 2; i++) {
        int row = wm * 32 + i * 16 + a_mh * 8 + lr;
        aOff[i] = row * 128; aR7[i] = row & 7;
    }
    int brow = wn * 16 + b_jl * 8 + lr;
    uint32_t bOff = brow * 128; int bR7 = brow & 7;

    float colfac[2][2];
#pragma unroll
    for (int jf = 0; jf < 2; jf++)
#pragma unroll
        for (int lb = 0; lb < 2; lb++) {
            int dj = wn * 16 + jf * 8 + qc + lb;
            colfac[jf][lb] = exp2f(-log2g * (float)dj) * scale;
        }

#pragma unroll
    for (int l = 0; l < 8; l++) {
        int idx = tid + l * 256;
        int arr = idx >> 10, ct = (idx >> 9) & 1, r = (idx >> 3) & 63, c = idx & 7;
        const __nv_bfloat16* src = (arr ? Qlg : Qhg) + (size_t)(i0 + r) * DIM + ct * 64 + c * 8;
        uint32_t dst = sb + (arr ? OQL : OQH) + ct * 8192 + r * 128 + (((c ^ (r & 7))) << 4);
        cp16(dst, src);
    }
    at_load_kv(sb + OKV, Khg, Klg, Vhg, Vlg, 0, tid);
    asm volatile("cp.async.commit_group;" ::: "memory");

    float yacc[2][4][4];
#pragma unroll
    for (int i = 0; i < 2; i++)
#pragma unroll
        for (int t = 0; t < 4; t++)
#pragma unroll
            for (int q = 0; q < 4; q++) yacc[i][t][q] = 0.f;

    for (int jt = 0; jt <= it; jt++) {
        int j0 = jt * 64;
        uint32_t kvb = sb + OKV + (jt & 1) * KVBUF;

        asm volatile("cp.async.wait_group 0;" ::: "memory");
        __syncthreads();

        if (jt < it) {
            at_load_kv(sb + OKV + ((jt + 1) & 1) * KVBUF, Khg, Klg, Vhg, Vlg, j0 + 64, tid);
            asm volatile("cp.async.commit_group;" ::: "memory");
        }

        float acc1[2][2][4];
#pragma unroll
        for (int i = 0; i < 2; i++)
#pragma unroll
            for (int j = 0; j < 2; j++)
#pragma unroll
                for (int q = 0; q < 4; q++) acc1[i][j][q] = 0.f;

#pragma unroll
        for (int ct = 0; ct < 2; ct++) {
#pragma unroll
            for (int ks = 0; ks < 4; ks++) {
                int ca = ks * 2 + a_kh;
                int cb = ks * 2 + b_kh;
                uint32_t qh[2][4], ql[2][4], bh[4], bl[4];
#pragma unroll
                for (int i = 0; i < 2; i++) {
                    ldx4(qh[i], sb + OQH + ct * 8192 + aOff[i] + (((uint32_t)(ca ^ aR7[i])) << 4));
                    ldx4(ql[i], sb + OQL + ct * 8192 + aOff[i] + (((uint32_t)(ca ^ aR7[i])) << 4));
                }
                ldx4(bh, kvb + OKH + ct * 8192 + bOff + (((uint32_t)(cb ^ bR7)) << 4));
                ldx4(bl, kvb + OKL + ct * 8192 + bOff + (((uint32_t)(cb ^ bR7)) << 4));
#pragma unroll
                for (int i = 0; i < 2; i++)
#pragma unroll
                    for (int j = 0; j < 2; j++) {
                        mma16816(acc1[i][j], qh[i], bh[2 * j], bh[2 * j + 1]);
                        mma16816(acc1[i][j], qh[i], bl[2 * j], bl[2 * j + 1]);
                        mma16816(acc1[i][j], ql[i], bh[2 * j], bh[2 * j + 1]);
                    }
            }
        }

        float rowfac[2][2];
#pragma unroll
        for (int i = 0; i < 2; i++)
#pragma unroll
            for (int h = 0; h < 2; h++) {
                int rrel = i0 - j0 + wm * 32 + i * 16 + qr + h * 8;
                rowfac[i][h] = exp2f(log2g * (float)rrel);
            }
#pragma unroll
        for (int i = 0; i < 2; i++)
#pragma unroll
            for (int j = 0; j < 2; j++)
#pragma unroll
                for (int h = 0; h < 2; h++) {
                    int row = wm * 32 + i * 16 + qr + h * 8;
                    int col = wn * 16 + j * 8 + qc;
                    int diff0 = (i0 + row) - (j0 + col);
                    float v0 = (diff0 >= 0) ? acc1[i][j][h * 2 + 0] * rowfac[i][h] * colfac[j][0] : 0.f;
                    float v1 = (diff0 >= 1) ? acc1[i][j][h * 2 + 1] * rowfac[i][h] * colfac[j][1] : 0.f;
                    __nv_bfloat16 h0 = __float2bfloat16(v0), h1 = __float2bfloat16(v1);
                    __nv_bfloat16 l0 = __float2bfloat16(v0 - __bfloat162float(h0));
                    __nv_bfloat16 l1 = __float2bfloat16(v1 - __bfloat162float(h1));
                    uint32_t off = row * 128 + ((((col >> 3) ^ (row & 7))) << 4) + (col & 7) * 2;
                    *(__nv_bfloat162*)(smem + OSH + off) = __nv_bfloat162(h0, h1);
                    *(__nv_bfloat162*)(smem + OSL + off) = __nv_bfloat162(l0, l1);
                }
        __syncthreads();

#pragma unroll
        for (int ks = 0; ks < 4; ks++) {
            int ca = ks * 2 + a_kh;
            uint32_t sh[2][4], sl[2][4], vh[2][4], vl[2][4];
#pragma unroll
            for (int i = 0; i < 2; i++) {
                ldx4(sh[i], sb + OSH + aOff[i] + (((uint32_t)(ca ^ aR7[i])) << 4));
                ldx4(sl[i], sb + OSL + aOff[i] + (((uint32_t)(ca ^ aR7[i])) << 4));
            }
            int vrow = ks * 16 + v_m * 8 + lr;
#pragma unroll
            for (int g = 0; g < 2; g++) {
                int dc = wn * 4 + g * 2 + v_g;
                uint32_t vo = vrow * 256 + (((uint32_t)(dc ^ (vrow & 7))) << 4);
                ldx4t(vh[g], kvb + OVH + vo);
                ldx4t(vl[g], kvb + OVL + vo);
            }
#pragma unroll
            for (int i = 0; i < 2; i++)
#pragma unroll
                for (int t = 0; t < 4; t++) {
                    int g = t >> 1, s2 = (t & 1) * 2;
                    mma16816(yacc[i][t], sh[i], vh[g][s2], vh[g][s2 + 1]);
                    mma16816(yacc[i][t], sh[i], vl[g][s2], vl[g][s2 + 1]);
                    mma16816(yacc[i][t], sl[i], vh[g][s2], vh[g][s2 + 1]);
                }
        }
    }

#pragma unroll
    for (int i = 0; i < 2; i++) {
        int row = i0 + wm * 32 + i * 16 + qr;
#pragma unroll
        for (int t = 0; t < 4; t++) {
            float* yp = g_Y + (size_t)row * DIM + head * HDIM + wn * 32 + t * 8 + qc;
            *(float2*)yp = make_float2(yacc[i][t][0], yacc[i][t][1]);
            *(float2*)(yp + 8 * DIM) = make_float2(yacc[i][t][2], yacc[i][t][3]);
        }
    }
}

// ---------------------------------------------------------------------------
// LayerNorm(Y) * silu(G) -> bf16 hi + lo arrays
// ---------------------------------------------------------------------------
__global__ __launch_bounds__(256) void ln_silu_gate(const float* __restrict__ lnw,
                                                    const float* __restrict__ lnb,
                                                    __nv_bfloat16* __restrict__ ohi,
                                                    __nv_bfloat16* __restrict__ olo) {
    int row = blockIdx.x;
    const float* y = g_Y + (size_t)row * DIM;
    const float* g = g_G + (size_t)row * DIM;
    int tid = threadIdx.x;

    float vals[8];
    float s = 0.f, ss = 0.f;
#pragma unroll
    for (int i = 0; i < 2; i++) {
        float4 v = *(const float4*)(y + tid * 4 + i * 1024);
        vals[i * 4 + 0] = v.x; vals[i * 4 + 1] = v.y;
        vals[i * 4 + 2] = v.z; vals[i * 4 + 3] = v.w;
        s += v.x + v.y + v.z + v.w;
        ss += v.x * v.x + v.y * v.y + v.z * v.z + v.w * v.w;
    }
#pragma unroll
    for (int off = 16; off > 0; off >>= 1) {
        s += __shfl_xor_sync(0xFFFFFFFFu, s, off);
        ss += __shfl_xor_sync(0xFFFFFFFFu, ss, off);
    }
    __shared__ float rs[8], rss[8];
    if ((tid & 31) == 0) { rs[tid >> 5] = s; rss[tid >> 5] = ss; }
    __syncthreads();
    s = 0.f; ss = 0.f;
#pragma unroll
    for (int i = 0; i < 8; i++) { s += rs[i]; ss += rss[i]; }

    float mu = s * (1.0f / DIM);
    float var = ss * (1.0f / DIM) - mu * mu;
    float rstd = rsqrtf(var + 1e-5f);

#pragma unroll
    for (int i = 0; i < 2; i++) {
        int c0 = tid * 4 + i * 1024;
        float4 gv = *(const float4*)(g + c0);
        float4 wv = *(const float4*)(lnw + c0);
        float4 bv = *(const float4*)(lnb + c0);
        float o[4];
        o[0] = ((vals[i * 4 + 0] - mu) * rstd * wv.x + bv.x) * (gv.x / (1.0f + expf(-gv.x)));
        o[1] = ((vals[i * 4 + 1] - mu) * rstd * wv.y + bv.y) * (gv.y / (1.0f + expf(-gv.y)));
        o[2] = ((vals[i * 4 + 2] - mu) * rstd * wv.z + bv.z) * (gv.z / (1.0f + expf(-gv.z)));
        o[3] = ((vals[i * 4 + 3] - mu) * rstd * wv.w + bv.w) * (gv.w / (1.0f + expf(-gv.w)));
        __nv_bfloat16 h[4], l[4];
#pragma unroll
        for (int j = 0; j < 4; j++) {
            h[j] = __float2bfloat16(o[j]);
            l[j] = __float2bfloat16(o[j] - __bfloat162float(h[j]));
        }
        size_t base = (size_t)row * DIM + c0;
        *(__nv_bfloat162*)(ohi + base)     = __nv_bfloat162(h[0], h[1]);
        *(__nv_bfloat162*)(ohi + base + 2) = __nv_bfloat162(h[2], h[3]);
        *(__nv_bfloat162*)(olo + base)     = __nv_bfloat162(l[0], l[1]);
        *(__nv_bfloat162*)(olo + base + 2) = __nv_bfloat162(l[2], l[3]);
    }
}

// ---------------------------------------------------------------------------
typedef CUresult (*EncodeFn)(CUtensorMap*, CUtensorMapDataType, cuuint32_t, void*,
                             const cuuint64_t*, const cuuint64_t*, const cuuint32_t*,
                             const cuuint32_t*, CUtensorMapInterleave, CUtensorMapSwizzle,
                             CUtensorMapL2promotion, CUtensorMapFloatOOBfill);

static void make_map2d(EncodeFn enc, CUtensorMap* m, void* ptr, uint32_t box_rows) {
    cuuint64_t dims[2] = {DIM, SEQ};
    cuuint64_t strides[1] = {DIM * 2};
    cuuint32_t box[2] = {64, box_rows};
    cuuint32_t es[2] = {1, 1};
    enc(m, CU_TENSOR_MAP_DATA_TYPE_BFLOAT16, 2, ptr, dims, strides, box, es,
        CU_TENSOR_MAP_INTERLEAVE_NONE, CU_TENSOR_MAP_SWIZZLE_128B,
        CU_TENSOR_MAP_L2_PROMOTION_L2_128B, CU_TENSOR_MAP_FLOAT_OOB_FILL_NONE);
}

extern "C" void kernel_launch(void* const* d_in, const int* in_sizes, int n_in,
                              void* d_out, int out_size) {
    const float* x   = (const float*)d_in[0];
    const float* wq  = (const float*)d_in[1];
    const float* wk  = (const float*)d_in[2];
    const float* wv  = (const float*)d_in[3];
    const float* wg  = (const float*)d_in[4];
    const float* wo  = (const float*)d_in[5];
    const float* lnw = (const float*)d_in[6];
    const float* lnb = (const float*)d_in[7];
    float* out = (float*)d_out;

    float *G;
    __nv_bfloat16 *xhi, *xlo, *ahi, *alo;
    __nv_bfloat16 *whi[5], *wlo[5];
    __nv_bfloat16 *qhi, *qlo, *khi, *klo, *vhi, *vlo;
    cudaGetSymbolAddress((void**)&G, g_G);
    cudaGetSymbolAddress((void**)&xhi, g_xhi);  cudaGetSymbolAddress((void**)&xlo, g_xlo);
    cudaGetSymbolAddress((void**)&ahi, g_ahi);  cudaGetSymbolAddress((void**)&alo, g_alo);
    cudaGetSymbolAddress((void**)&whi[0], g_wqhi); cudaGetSymbolAddress((void**)&wlo[0], g_wqlo);
    cudaGetSymbolAddress((void**)&whi[1], g_wkhi); cudaGetSymbolAddress((void**)&wlo[1], g_wklo);
    cudaGetSymbolAddress((void**)&whi[2], g_wvhi); cudaGetSymbolAddress((void**)&wlo[2], g_wvlo);
    cudaGetSymbolAddress((void**)&whi[3], g_wghi); cudaGetSymbolAddress((void**)&wlo[3], g_wglo);
    cudaGetSymbolAddress((void**)&whi[4], g_wohi); cudaGetSymbolAddress((void**)&wlo[4], g_wolo);
    cudaGetSymbolAddress((void**)&qhi, g_Qhi); cudaGetSymbolAddress((void**)&qlo, g_Qlo);
    cudaGetSymbolAddress((void**)&khi, g_Khi); cudaGetSymbolAddress((void**)&klo, g_Klo);
    cudaGetSymbolAddress((void**)&vhi, g_Vhi); cudaGetSymbolAddress((void**)&vlo, g_Vlo);

    static CUtensorMap h_maps[14];
    void* encPtr = nullptr;
    cudaDriverEntryPointQueryResult qres;
    cudaGetDriverEntryPoint("cuTensorMapEncodeTiled", &encPtr, cudaEnableDefault, &qres);
    EncodeFn enc = (EncodeFn)encPtr;
    make_map2d(enc, &h_maps[0], xhi, 128);
    make_map2d(enc, &h_maps[1], xlo, 128);
    make_map2d(enc, &h_maps[2], ahi, 128);
    make_map2d(enc, &h_maps[3], alo, 128);
    for (int p = 0; p < 5; p++) {
        make_map2d(enc, &h_maps[4 + 2 * p],     whi[p], 256);
        make_map2d(enc, &h_maps[4 + 2 * p + 1], wlo[p], 256);
    }
    cudaMemcpyToSymbolAsync(g_tmaps, h_maps, sizeof(h_maps), 0, cudaMemcpyHostToDevice, 0);
    CUtensorMap* tm;
    cudaGetSymbolAddress((void**)&tm, g_tmaps);

    cudaFuncSetAttribute(gemm3,   cudaFuncAttributeMaxDynamicSharedMemorySize, GEMM_SMEM);
    cudaFuncSetAttribute(gemm3x4, cudaFuncAttributeMaxDynamicSharedMemorySize, GEMM_SMEM);
    cudaFuncSetAttribute(retention_tc, cudaFuncAttributeMaxDynamicSharedMemorySize, AT_SMEM);

    cvt6<<<dim3(1024, 6), 256>>>(x,  xhi,    xlo,
                                 wq, whi[0], wlo[0],
                                 wk, whi[1], wlo[1],
                                 wv, whi[2], wlo[2],
                                 wg, whi[3], wlo[3],
                                 wo, whi[4], wlo[4]);

    gemm3x4<<<dim3(DIM / GBN, SEQ / GBM, 4), GTHREADS, GEMM_SMEM>>>(
        tm, qhi, qlo, khi, klo, vhi, vlo, G);

    retention_tc<<<dim3(SEQ / 64, NH), 256, AT_SMEM>>>();

    ln_silu_gate<<<SEQ, 256>>>(lnw, lnb, ahi, alo);

    gemm3<<<dim3(DIM / GBN, SEQ / GBM), GTHREADS, GEMM_SMEM>>>(tm + 2, tm + 3, tm + 12, tm + 13, out);
}

// round 16
// speedup vs baseline: 1.0743x; 1.0025x over previous
#include <cuda_runtime.h>
#include <cuda.h>
#include <cuda_bf16.h>
#include <math.h>
#include <cstdint>
#include <cstring>

#define SEQ 2048
#define DIM 2048
#define NH 16
#define HDIM 128

// ------------------------- scratch (device globals) -------------------------
__device__ float g_G[SEQ * DIM];
__device__ float g_Y[SEQ * DIM];

__device__ __nv_bfloat16 g_xhi[SEQ * DIM],  g_xlo[SEQ * DIM];
__device__ __nv_bfloat16 g_wqhi[DIM * DIM], g_wqlo[DIM * DIM];
__device__ __nv_bfloat16 g_wkhi[DIM * DIM], g_wklo[DIM * DIM];
__device__ __nv_bfloat16 g_wvhi[DIM * DIM], g_wvlo[DIM * DIM];
__device__ __nv_bfloat16 g_wghi[DIM * DIM], g_wglo[DIM * DIM];
__device__ __nv_bfloat16 g_wohi[DIM * DIM], g_wolo[DIM * DIM];
__device__ __nv_bfloat16 g_Qhi[SEQ * DIM],  g_Qlo[SEQ * DIM];
__device__ __nv_bfloat16 g_Khi[SEQ * DIM],  g_Klo[SEQ * DIM];
__device__ __nv_bfloat16 g_Vhi[SEQ * DIM],  g_Vlo[SEQ * DIM];
__device__ __nv_bfloat16 g_ahi[SEQ * DIM],  g_alo[SEQ * DIM];

__device__ CUtensorMap g_tmaps[14];

// ------------------------- helpers -------------------------
__device__ __forceinline__ uint32_t smem_u32(const void* p) {
    uint32_t a;
    asm("{ .reg .u64 t; cvta.to.shared.u64 t, %1; cvt.u32.u64 %0, t; }" : "=r"(a) : "l"(p));
    return a;
}
__device__ __forceinline__ void cp16(uint32_t dst, const void* src) {
    asm volatile("cp.async.cg.shared.global [%0], [%1], 16;" :: "r"(dst), "l"(src));
}
__device__ __forceinline__ void ldx4(uint32_t* r, uint32_t addr) {
    asm volatile("ldmatrix.sync.aligned.m8n8.x4.shared.b16 {%0,%1,%2,%3}, [%4];"
                 : "=r"(r[0]), "=r"(r[1]), "=r"(r[2]), "=r"(r[3]) : "r"(addr));
}
__device__ __forceinline__ void ldx4t(uint32_t* r, uint32_t addr) {
    asm volatile("ldmatrix.sync.aligned.m8n8.x4.trans.shared.b16 {%0,%1,%2,%3}, [%4];"
                 : "=r"(r[0]), "=r"(r[1]), "=r"(r[2]), "=r"(r[3]) : "r"(addr));
}
__device__ __forceinline__ void mma16816(float* c, const uint32_t* a, uint32_t b0, uint32_t b1) {
    asm volatile(
        "mma.sync.aligned.m16n8k16.row.col.f32.bf16.bf16.f32 "
        "{%0,%1,%2,%3}, {%4,%5,%6,%7}, {%8,%9}, {%0,%1,%2,%3};"
        : "+f"(c[0]), "+f"(c[1]), "+f"(c[2]), "+f"(c[3])
        : "r"(a[0]), "r"(a[1]), "r"(a[2]), "r"(a[3]), "r"(b0), "r"(b1));
}

#define MBARRIER_INIT(addr, cnt) \
    asm volatile("mbarrier.init.shared.b64 [%0], %1;" :: "r"(addr), "r"(cnt) : "memory")
#define MBARRIER_ARRIVE(addr) \
    asm volatile("mbarrier.arrive.shared.b64 _, [%0];" :: "r"(addr) : "memory")
#define MBARRIER_EXPECT_TX(addr, bytes) \
    asm volatile("mbarrier.arrive.expect_tx.shared.b64 _, [%0], %1;" :: "r"(addr), "r"(bytes) : "memory")
#define MBARRIER_WAIT_PARITY(addr, par) do { \
    uint32_t _m = (addr); uint32_t _p = (par); uint32_t _d; \
    asm volatile("{ .reg .pred p; mbarrier.try_wait.parity.acquire.cta.shared::cta.b64 p, [%1], %2; selp.b32 %0,1,0,p; }" \
        : "=r"(_d) : "r"(_m), "r"(_p) : "memory"); \
    if (!_d) { \
        asm volatile("{ .reg .pred P1; WL_%=: mbarrier.try_wait.parity.acquire.cta.shared::cta.b64 P1, [%0], %1, 0x989680; @P1 bra.uni WD_%=; bra.uni WL_%=; WD_%=: }" \
            :: "r"(_m), "r"(_p) : "memory"); \
    } \
} while (0)
#define TMA_LOAD_2D(smem_addr, map, cx, cy, mbar) \
    asm volatile("cp.async.bulk.tensor.2d.shared::cta.global.tile.mbarrier::complete_tx::bytes " \
                 "[%0], [%1, {%2, %3}], [%4];" \
                 :: "r"(smem_addr), "l"(map), "r"(cx), "r"(cy), "r"(mbar) : "memory")

// ---------------------------------------------------------------------------
// Fused 3-pass hi/lo bf16 GEMM body (TN). Tile 128x256, BK=64, 512 thr (4x4).
// TMA + full/empty mbarrier ring; per-warp (lane0) empty arrives, count=16.
// ---------------------------------------------------------------------------
static constexpr int GBM = 128, GBN = 256, GBK = 64;
static constexpr int GTHREADS = 512;
static constexpr int NCH = DIM / GBK;
static constexpr int OF_AH = 0;
static constexpr int OF_AL = 16384;
static constexpr int OF_BH = 32768;
static constexpr int OF_BL = 65536;
static constexpr int GBUF = 98304;
static constexpr int GEMM_SMEM = 2 * GBUF + 64;

__device__ __forceinline__ void tma_chunk(uint32_t buf, const CUtensorMap* mAh,
                                          const CUtensorMap* mAl, const CUtensorMap* mBh,
                                          const CUtensorMap* mBl, int m0, int n0, int kc,
                                          uint32_t bar) {
    MBARRIER_EXPECT_TX(bar, (uint32_t)GBUF);
    TMA_LOAD_2D(buf + OF_AH, mAh, kc, m0, bar);
    TMA_LOAD_2D(buf + OF_AL, mAl, kc, m0, bar);
    TMA_LOAD_2D(buf + OF_BH, mBh, kc, n0, bar);
    TMA_LOAD_2D(buf + OF_BL, mBl, kc, n0, bar);
}

__device__ __forceinline__ void gemm3_body(const CUtensorMap* mAh, const CUtensorMap* mAl,
                                           const CUtensorMap* mBh, const CUtensorMap* mBl,
                                           float* C, __nv_bfloat16* Chi, __nv_bfloat16* Clo,
                                           int mode, char* smem, int m0, int n0) {
    uint32_t sb = smem_u32(smem);
    uint32_t full0 = sb + 2 * GBUF, full1 = full0 + 8;
    uint32_t empty0 = full1 + 8, empty1 = empty0 + 8;
    int tid = threadIdx.x;
    int wid = tid >> 5, lane = tid & 31;
    int wm = wid & 3, wn = wid >> 2;

    if (tid == 0) {
        asm volatile("prefetch.tensormap [%0];" :: "l"(mAh));
        asm volatile("prefetch.tensormap [%0];" :: "l"(mAl));
        asm volatile("prefetch.tensormap [%0];" :: "l"(mBh));
        asm volatile("prefetch.tensormap [%0];" :: "l"(mBl));
        MBARRIER_INIT(full0, 1);
        MBARRIER_INIT(full1, 1);
        MBARRIER_INIT(empty0, 16);
        MBARRIER_INIT(empty1, 16);
    }
    __syncthreads();
    if (tid == 0) {
        tma_chunk(sb, mAh, mAl, mBh, mBl, m0, n0, 0, full0);
        tma_chunk(sb + GBUF, mAh, mAl, mBh, mBl, m0, n0, GBK, full1);
    }

    int a_mh = (lane >> 3) & 1, a_kh = lane >> 4, lr = lane & 7;
    uint32_t aOff[2]; int aR7[2];
#pragma unroll
    for (int i = 0; i < 2; i++) {
        int row = wm * 32 + i * 16 + a_mh * 8 + lr;
        aOff[i] = row * 128; aR7[i] = row & 7;
    }
    int b_jl = lane >> 4, b_kh = (lane >> 3) & 1;
    uint32_t bOff[4]; int bR7[4];
#pragma unroll
    for (int p = 0; p < 4; p++) {
        int row = wn * 64 + p * 16 + b_jl * 8 + lr;
        bOff[p] = row * 128; bR7[p] = row & 7;
    }

    float acc[2][8][4];
#pragma unroll
    for (int i = 0; i < 2; i++)
#pragma unroll
        for (int j = 0; j < 8; j++)
#pragma unroll
            for (int q = 0; q < 4; q++) acc[i][j][q] = 0.f;

    for (int t = 0; t < NCH; t++) {
        uint32_t full  = (t & 1) ? full1 : full0;
        uint32_t empty = (t & 1) ? empty1 : empty0;
        MBARRIER_WAIT_PARITY(full, (t >> 1) & 1);

        uint32_t buf = sb + (t & 1) * GBUF;
#pragma unroll
        for (int ks = 0; ks < 4; ks++) {
            int ca = ks * 2 + a_kh;
            int cb = ks * 2 + b_kh;
            uint32_t ah[2][4], al[2][4];
#pragma unroll
            for (int i = 0; i < 2; i++) {
                ldx4(ah[i], buf + OF_AH + aOff[i] + (((uint32_t)(ca ^ aR7[i])) << 4));
                ldx4(al[i], buf + OF_AL + aOff[i] + (((uint32_t)(ca ^ aR7[i])) << 4));
            }
#pragma unroll
            for (int ph = 0; ph < 2; ph++) {
                uint32_t bh[2][4], bl[2][4];
#pragma unroll
                for (int p2 = 0; p2 < 2; p2++) {
                    int p = ph * 2 + p2;
                    ldx4(bh[p2], buf + OF_BH + bOff[p] + (((uint32_t)(cb ^ bR7[p])) << 4));
                    ldx4(bl[p2], buf + OF_BL + bOff[p] + (((uint32_t)(cb ^ bR7[p])) << 4));
                }
#pragma unroll
                for (int i = 0; i < 2; i++)
#pragma unroll
                    for (int j4 = 0; j4 < 4; j4++) {
                        int j = ph * 4 + j4;
                        int p2 = j4 >> 1, jl = j4 & 1;
                        mma16816(acc[i][j], ah[i], bh[p2][2 * jl], bh[p2][2 * jl + 1]);
                        mma16816(acc[i][j], ah[i], bl[p2][2 * jl], bl[p2][2 * jl + 1]);
                        mma16816(acc[i][j], al[i], bh[p2][2 * jl], bh[p2][2 * jl + 1]);
                    }
            }
        }

        if (lane == 0) MBARRIER_ARRIVE(empty);   // per-warp consume signal (count 16)
        if (t + 2 < NCH && tid == 0) {
            MBARRIER_WAIT_PARITY(empty, (t >> 1) & 1);
            tma_chunk(buf, mAh, mAl, mBh, mBl, m0, n0, (t + 2) * GBK, full);
        }
    }

    int qr = lane >> 2, qc = (lane & 3) * 2;
#pragma unroll
    for (int i = 0; i < 2; i++) {
        int mrow = m0 + wm * 32 + i * 16 + qr;
#pragma unroll
        for (int j = 0; j < 8; j++) {
            size_t base = (size_t)mrow * DIM + n0 + wn * 64 + j * 8 + qc;
            if (mode == 0) {
                C[base]               = acc[i][j][0];
                C[base + 1]           = acc[i][j][1];
                C[base + 8 * DIM]     = acc[i][j][2];
                C[base + 8 * DIM + 1] = acc[i][j][3];
            } else {
#pragma unroll
                for (int h2 = 0; h2 < 2; h2++) {
                    float v0 = acc[i][j][h2 * 2], v1 = acc[i][j][h2 * 2 + 1];
                    __nv_bfloat16 h0 = __float2bfloat16(v0), h1 = __float2bfloat16(v1);
                    __nv_bfloat16 l0 = __float2bfloat16(v0 - __bfloat162float(h0));
                    __nv_bfloat16 l1 = __float2bfloat16(v1 - __bfloat162float(h1));
                    size_t bb = base + h2 * 8 * DIM;
                    *(__nv_bfloat162*)(Chi + bb) = __nv_bfloat162(h0, h1);
                    *(__nv_bfloat162*)(Clo + bb) = __nv_bfloat162(l0, l1);
                }
            }
        }
    }
}

// final wo projection: single GEMM
__global__ __launch_bounds__(GTHREADS, 1) void gemm3(const CUtensorMap* __restrict__ mAh,
                                                     const CUtensorMap* __restrict__ mAl,
                                                     const CUtensorMap* __restrict__ mBh,
                                                     const CUtensorMap* __restrict__ mBl,
                                                     float* __restrict__ C) {
    extern __shared__ char smem[];
    gemm3_body(mAh, mAl, mBh, mBl, C, nullptr, nullptr, 0, smem,
               blockIdx.y * GBM, blockIdx.x * GBN);
}

// merged Q/K/V/G projections: grid (8, 16, 4), z selects weight/output.
__global__ __launch_bounds__(GTHREADS, 1) void gemm3x4(
    const CUtensorMap* __restrict__ tm,
    __nv_bfloat16* __restrict__ qhi, __nv_bfloat16* __restrict__ qlo,
    __nv_bfloat16* __restrict__ khi, __nv_bfloat16* __restrict__ klo,
    __nv_bfloat16* __restrict__ vhi, __nv_bfloat16* __restrict__ vlo,
    float* __restrict__ G) {
    extern __shared__ char smem[];
    int z = blockIdx.z;
    const CUtensorMap* mBh = tm + 4 + 2 * z;
    const CUtensorMap* mBl = tm + 5 + 2 * z;
    __nv_bfloat16 *Chi = nullptr, *Clo = nullptr;
    float* Cf = nullptr;
    int mode;
    if (z == 0)      { Chi = qhi; Clo = qlo; mode = 1; }
    else if (z == 1) { Chi = khi; Clo = klo; mode = 1; }
    else if (z == 2) { Chi = vhi; Clo = vlo; mode = 1; }
    else             { Cf = G;               mode = 0; }
    gemm3_body(tm + 0, tm + 1, mBh, mBl, Cf, Chi, Clo, mode, smem,
               blockIdx.y * GBM, blockIdx.x * GBN);
}

// ---------------------------------------------------------------------------
// fp32 -> bf16 hi/lo, all 6 tensors in one launch; 8 float4/thread (MLP=8)
// ---------------------------------------------------------------------------
__global__ __launch_bounds__(256) void cvt6(
    const float* s0, __nv_bfloat16* h0, __nv_bfloat16* l0,
    const float* s1, __nv_bfloat16* h1, __nv_bfloat16* l1,
    const float* s2, __nv_bfloat16* h2, __nv_bfloat16* l2,
    const float* s3, __nv_bfloat16* h3, __nv_bfloat16* l3,
    const float* s4, __nv_bfloat16* h4, __nv_bfloat16* l4,
    const float* s5, __nv_bfloat16* h5, __nv_bfloat16* l5) {
    const float* s; __nv_bfloat16 *hi, *lo;
    switch (blockIdx.y) {
        case 0: s = s0; hi = h0; lo = l0; break;
        case 1: s = s1; hi = h1; lo = l1; break;
        case 2: s = s2; hi = h2; lo = l2; break;
        case 3: s = s3; hi = h3; lo = l3; break;
        case 4: s = s4; hi = h4; lo = l4; break;
        default: s = s5; hi = h5; lo = l5; break;
    }
    int base = blockIdx.x * 2048 + threadIdx.x;
    float4 v[8];
#pragma unroll
    for (int u = 0; u < 8; u++) v[u] = ((const float4*)s)[base + u * 256];
#pragma unroll
    for (int u = 0; u < 8; u++) {
        int i = base + u * 256;
        __nv_bfloat16 a0 = __float2bfloat16(v[u].x), a1 = __float2bfloat16(v[u].y);
        __nv_bfloat16 a2 = __float2bfloat16(v[u].z), a3 = __float2bfloat16(v[u].w);
        __nv_bfloat16 b0 = __float2bfloat16(v[u].x - __bfloat162float(a0));
        __nv_bfloat16 b1 = __float2bfloat16(v[u].y - __bfloat162float(a1));
        __nv_bfloat16 b2 = __float2bfloat16(v[u].z - __bfloat162float(a2));
        __nv_bfloat16 b3 = __float2bfloat16(v[u].w - __bfloat162float(a3));
        ((__nv_bfloat162*)hi)[2 * i]     = __nv_bfloat162(a0, a1);
        ((__nv_bfloat162*)hi)[2 * i + 1] = __nv_bfloat162(a2, a3);
        ((__nv_bfloat162*)lo)[2 * i]     = __nv_bfloat162(b0, b1);
        ((__nv_bfloat162*)lo)[2 * i + 1] = __nv_bfloat162(b2, b3);
    }
}

// ---------------------------------------------------------------------------
// Tensor-core retention attention (BI=BJ=64, 8 warps, K/V double-buffered).
// grid (32 i-tiles, 16 heads), 256 threads. (round-11 version — known good)
// ---------------------------------------------------------------------------
static constexpr int KVBUF = 65536;
static constexpr int OQH = 0, OQL = 16384;
static constexpr int OKV = 32768;
static constexpr int OKH = 0, OKL = 16384, OVH = 32768, OVL = 49152;
static constexpr int OSH = 163840, OSL = 172032;
static constexpr int AT_SMEM = 180224;

__device__ __forceinline__ void at_load_kv(uint32_t kvbase,
                                           const __nv_bfloat16* Khg, const __nv_bfloat16* Klg,
                                           const __nv_bfloat16* Vhg, const __nv_bfloat16* Vlg,
                                           int j0, int tid) {
#pragma unroll
    for (int l = 0; l < 8; l++) {
        int idx = tid + l * 256;
        int arr = idx >> 10, ct = (idx >> 9) & 1, r = (idx >> 3) & 63, c = idx & 7;
        const __nv_bfloat16* src = (arr ? Klg : Khg) + (size_t)(j0 + r) * DIM + ct * 64 + c * 8;
        uint32_t dst = kvbase + (arr ? OKL : OKH) + ct * 8192 + r * 128 + (((c ^ (r & 7))) << 4);
        cp16(dst, src);
    }
#pragma unroll
    for (int l = 0; l < 8; l++) {
        int idx = tid + l * 256;
        int arr = idx >> 10, r = (idx >> 4) & 63, dc = idx & 15;
        const __nv_bfloat16* src = (arr ? Vlg : Vhg) + (size_t)(j0 + r) * DIM + dc * 8;
        uint32_t dst = kvbase + (arr ? OVL : OVH) + r * 256 + (((dc ^ (r & 7))) << 4);
        cp16(dst, src);
    }
}

__global__ __launch_bounds__(256, 1) void retention_tc() {
    extern __shared__ char smem[];
    uint32_t sb = smem_u32(smem);

    int head = blockIdx.y;
    int it = gridDim.x - 1 - blockIdx.x;
    int i0 = it * 64;
    int tid = threadIdx.x, lane = tid & 31, wid = tid >> 5;
    int wm = wid & 1, wn = wid >> 1;

    const float lg0 = -3.4657359027997265f;
    const float lg1 = -6.2383246250395075f;
    float gamma = 1.0f - expf(lg0 + (lg1 - lg0) * ((float)head * (1.0f / 15.0f)));
    float log2g = log2f(gamma);
    const float scale = 0.088388347648318447f;

    const __nv_bfloat16* Qhg = g_Qhi + head * HDIM;
    const __nv_bfloat16* Qlg = g_Qlo + head * HDIM;
    const __nv_bfloat16* Khg = g_Khi + head * HDIM;
    const __nv_bfloat16* Klg = g_Klo + head * HDIM;
    const __nv_bfloat16* Vhg = g_Vhi + head * HDIM;
    const __nv_bfloat16* Vlg = g_Vlo + head * HDIM;

    int qr = lane >> 2, qc = (lane & 3) * 2;
    int a_mh = (lane >> 3) & 1, a_kh = lane >> 4, lr = lane & 7;
    int b_jl = lane >> 4, b_kh = (lane >> 3) & 1;
    int v_m = (lane >> 3) & 1, v_g = lane >> 4;

    uint32_t aOff[2]; int aR7[2];
#pragma unroll
    for (int i = 0; i < 2; i++) {
        int row = wm * 32 + i * 16 + a_mh * 8 + lr;
        aOff[i] = row * 128; aR7[i] = row & 7;
    }
    int brow = wn * 16 + b_jl * 8 + lr;
    uint32_t bOff = brow * 128; int bR7 = brow & 7;

    float colfac[2][2];
#pragma unroll
    for (int jf = 0; jf < 2; jf++)
#pragma unroll
        for (int lb = 0; lb < 2; lb++) {
            int dj = wn * 16 + jf * 8 + qc + lb;
            colfac[jf][lb] = exp2f(-log2g * (float)dj) * scale;
        }

#pragma unroll
    for (int l = 0; l < 8; l++) {
        int idx = tid + l * 256;
        int arr = idx >> 10, ct = (idx >> 9) & 1, r = (idx >> 3) & 63, c = idx & 7;
        const __nv_bfloat16* src = (arr ? Qlg : Qhg) + (size_t)(i0 + r) * DIM + ct * 64 + c * 8;
        uint32_t dst = sb + (arr ? OQL : OQH) + ct * 8192 + r * 128 + (((c ^ (r & 7))) << 4);
        cp16(dst, src);
    }
    at_load_kv(sb + OKV, Khg, Klg, Vhg, Vlg, 0, tid);
    asm volatile("cp.async.commit_group;" ::: "memory");

    float yacc[2][4][4];
#pragma unroll
    for (int i = 0; i < 2; i++)
#pragma unroll
        for (int t = 0; t < 4; t++)
#pragma unroll
            for (int q = 0; q < 4; q++) yacc[i][t][q] = 0.f;

    for (int jt = 0; jt <= it; jt++) {
        int j0 = jt * 64;
        uint32_t kvb = sb + OKV + (jt & 1) * KVBUF;

        asm volatile("cp.async.wait_group 0;" ::: "memory");
        __syncthreads();

        if (jt < it) {
            at_load_kv(sb + OKV + ((jt + 1) & 1) * KVBUF, Khg, Klg, Vhg, Vlg, j0 + 64, tid);
            asm volatile("cp.async.commit_group;" ::: "memory");
        }

        float acc1[2][2][4];
#pragma unroll
        for (int i = 0; i < 2; i++)
#pragma unroll
            for (int j = 0; j < 2; j++)
#pragma unroll
                for (int q = 0; q < 4; q++) acc1[i][j][q] = 0.f;

#pragma unroll
        for (int ct = 0; ct < 2; ct++) {
#pragma unroll
            for (int ks = 0; ks < 4; ks++) {
                int ca = ks * 2 + a_kh;
                int cb = ks * 2 + b_kh;
                uint32_t qh[2][4], ql[2][4], bh[4], bl[4];
#pragma unroll
                for (int i = 0; i < 2; i++) {
                    ldx4(qh[i], sb + OQH + ct * 8192 + aOff[i] + (((uint32_t)(ca ^ aR7[i])) << 4));
                    ldx4(ql[i], sb + OQL + ct * 8192 + aOff[i] + (((uint32_t)(ca ^ aR7[i])) << 4));
                }
                ldx4(bh, kvb + OKH + ct * 8192 + bOff + (((uint32_t)(cb ^ bR7)) << 4));
                ldx4(bl, kvb + OKL + ct * 8192 + bOff + (((uint32_t)(cb ^ bR7)) << 4));
#pragma unroll
                for (int i = 0; i < 2; i++)
#pragma unroll
                    for (int j = 0; j < 2; j++) {
                        mma16816(acc1[i][j], qh[i], bh[2 * j], bh[2 * j + 1]);
                        mma16816(acc1[i][j], qh[i], bl[2 * j], bl[2 * j + 1]);
                        mma16816(acc1[i][j], ql[i], bh[2 * j], bh[2 * j + 1]);
                    }
            }
        }

        float rowfac[2][2];
#pragma unroll
        for (int i = 0; i < 2; i++)
#pragma unroll
            for (int h = 0; h < 2; h++) {
                int rrel = i0 - j0 + wm * 32 + i * 16 + qr + h * 8;
                rowfac[i][h] = exp2f(log2g * (float)rrel);
            }
#pragma unroll
        for (int i = 0; i < 2; i++)
#pragma unroll
            for (int j = 0; j < 2; j++)
#pragma unroll
                for (int h = 0; h < 2; h++) {
                    int row = wm * 32 + i * 16 + qr + h * 8;
                    int col = wn * 16 + j * 8 + qc;
                    int diff0 = (i0 + row) - (j0 + col);
                    float v0 = (diff0 >= 0) ? acc1[i][j][h * 2 + 0] * rowfac[i][h] * colfac[j][0] : 0.f;
                    float v1 = (diff0 >= 1) ? acc1[i][j][h * 2 + 1] * rowfac[i][h] * colfac[j][1] : 0.f;
                    __nv_bfloat16 h0 = __float2bfloat16(v0), h1 = __float2bfloat16(v1);
                    __nv_bfloat16 l0 = __float2bfloat16(v0 - __bfloat162float(h0));
                    __nv_bfloat16 l1 = __float2bfloat16(v1 - __bfloat162float(h1));
                    uint32_t off = row * 128 + ((((col >> 3) ^ (row & 7))) << 4) + (col & 7) * 2;
                    *(__nv_bfloat162*)(smem + OSH + off) = __nv_bfloat162(h0, h1);
                    *(__nv_bfloat162*)(smem + OSL + off) = __nv_bfloat162(l0, l1);
                }
        __syncthreads();

#pragma unroll
        for (int ks = 0; ks < 4; ks++) {
            int ca = ks * 2 + a_kh;
            uint32_t sh[2][4], sl[2][4], vh[2][4], vl[2][4];
#pragma unroll
            for (int i = 0; i < 2; i++) {
                ldx4(sh[i], sb + OSH + aOff[i] + (((uint32_t)(ca ^ aR7[i])) << 4));
                ldx4(sl[i], sb + OSL + aOff[i] + (((uint32_t)(ca ^ aR7[i])) << 4));
            }
            int vrow = ks * 16 + v_m * 8 + lr;
#pragma unroll
            for (int g = 0; g < 2; g++) {
                int dc = wn * 4 + g * 2 + v_g;
                uint32_t vo = vrow * 256 + (((uint32_t)(dc ^ (vrow & 7))) << 4);
                ldx4t(vh[g], kvb + OVH + vo);
                ldx4t(vl[g], kvb + OVL + vo);
            }
#pragma unroll
            for (int i = 0; i < 2; i++)
#pragma unroll
                for (int t = 0; t < 4; t++) {
                    int g = t >> 1, s2 = (t & 1) * 2;
                    mma16816(yacc[i][t], sh[i], vh[g][s2], vh[g][s2 + 1]);
                    mma16816(yacc[i][t], sh[i], vl[g][s2], vl[g][s2 + 1]);
                    mma16816(yacc[i][t], sl[i], vh[g][s2], vh[g][s2 + 1]);
                }
        }
    }

#pragma unroll
    for (int i = 0; i < 2; i++) {
        int row = i0 + wm * 32 + i * 16 + qr;
#pragma unroll
        for (int t = 0; t < 4; t++) {
            float* yp = g_Y + (size_t)row * DIM + head * HDIM + wn * 32 + t * 8 + qc;
            *(float2*)yp = make_float2(yacc[i][t][0], yacc[i][t][1]);
            *(float2*)(yp + 8 * DIM) = make_float2(yacc[i][t][2], yacc[i][t][3]);
        }
    }
}

// ---------------------------------------------------------------------------
// LayerNorm(Y) * silu(G) -> bf16 hi + lo arrays
// ---------------------------------------------------------------------------
__global__ __launch_bounds__(256) void ln_silu_gate(const float* __restrict__ lnw,
                                                    const float* __restrict__ lnb,
                                                    __nv_bfloat16* __restrict__ ohi,
                                                    __nv_bfloat16* __restrict__ olo) {
    int row = blockIdx.x;
    const float* y = g_Y + (size_t)row * DIM;
    const float* g = g_G + (size_t)row * DIM;
    int tid = threadIdx.x;

    float vals[8];
    float s = 0.f, ss = 0.f;
#pragma unroll
    for (int i = 0; i < 2; i++) {
        float4 v = *(const float4*)(y + tid * 4 + i * 1024);
        vals[i * 4 + 0] = v.x; vals[i * 4 + 1] = v.y;
        vals[i * 4 + 2] = v.z; vals[i * 4 + 3] = v.w;
        s += v.x + v.y + v.z + v.w;
        ss += v.x * v.x + v.y * v.y + v.z * v.z + v.w * v.w;
    }
#pragma unroll
    for (int off = 16; off > 0; off >>= 1) {
        s += __shfl_xor_sync(0xFFFFFFFFu, s, off);
        ss += __shfl_xor_sync(0xFFFFFFFFu, ss, off);
    }
    __shared__ float rs[8], rss[8];
    if ((tid & 31) == 0) { rs[tid >> 5] = s; rss[tid >> 5] = ss; }
    __syncthreads();
    s = 0.f; ss = 0.f;
#pragma unroll
    for (int i = 0; i < 8; i++) { s += rs[i]; ss += rss[i]; }

    float mu = s * (1.0f / DIM);
    float var = ss * (1.0f / DIM) - mu * mu;
    float rstd = rsqrtf(var + 1e-5f);

#pragma unroll
    for (int i = 0; i < 2; i++) {
        int c0 = tid * 4 + i * 1024;
        float4 gv = *(const float4*)(g + c0);
        float4 wv = *(const float4*)(lnw + c0);
        float4 bv = *(const float4*)(lnb + c0);
        float o[4];
        o[0] = ((vals[i * 4 + 0] - mu) * rstd * wv.x + bv.x) * (gv.x / (1.0f + expf(-gv.x)));
        o[1] = ((vals[i * 4 + 1] - mu) * rstd * wv.y + bv.y) * (gv.y / (1.0f + expf(-gv.y)));
        o[2] = ((vals[i * 4 + 2] - mu) * rstd * wv.z + bv.z) * (gv.z / (1.0f + expf(-gv.z)));
        o[3] = ((vals[i * 4 + 3] - mu) * rstd * wv.w + bv.w) * (gv.w / (1.0f + expf(-gv.w)));
        __nv_bfloat16 h[4], l[4];
#pragma unroll
        for (int j = 0; j < 4; j++) {
            h[j] = __float2bfloat16(o[j]);
            l[j] = __float2bfloat16(o[j] - __bfloat162float(h[j]));
        }
        size_t base = (size_t)row * DIM + c0;
        *(__nv_bfloat162*)(ohi + base)     = __nv_bfloat162(h[0], h[1]);
        *(__nv_bfloat162*)(ohi + base + 2) = __nv_bfloat162(h[2], h[3]);
        *(__nv_bfloat162*)(olo + base)     = __nv_bfloat162(l[0], l[1]);
        *(__nv_bfloat162*)(olo + base + 2) = __nv_bfloat162(l[2], l[3]);
    }
}

// ---------------------------------------------------------------------------
typedef CUresult (*EncodeFn)(CUtensorMap*, CUtensorMapDataType, cuuint32_t, void*,
                             const cuuint64_t*, const cuuint64_t*, const cuuint32_t*,
                             const cuuint32_t*, CUtensorMapInterleave, CUtensorMapSwizzle,
                             CUtensorMapL2promotion, CUtensorMapFloatOOBfill);

static void make_map2d(EncodeFn enc, CUtensorMap* m, void* ptr, uint32_t box_rows) {
    cuuint64_t dims[2] = {DIM, SEQ};
    cuuint64_t strides[1] = {DIM * 2};
    cuuint32_t box[2] = {64, box_rows};
    cuuint32_t es[2] = {1, 1};
    enc(m, CU_TENSOR_MAP_DATA_TYPE_BFLOAT16, 2, ptr, dims, strides, box, es,
        CU_TENSOR_MAP_INTERLEAVE_NONE, CU_TENSOR_MAP_SWIZZLE_128B,
        CU_TENSOR_MAP_L2_PROMOTION_L2_128B, CU_TENSOR_MAP_FLOAT_OOB_FILL_NONE);
}

extern "C" void kernel_launch(void* const* d_in, const int* in_sizes, int n_in,
                              void* d_out, int out_size) {
    const float* x   = (const float*)d_in[0];
    const float* wq  = (const float*)d_in[1];
    const float* wk  = (const float*)d_in[2];
    const float* wv  = (const float*)d_in[3];
    const float* wg  = (const float*)d_in[4];
    const float* wo  = (const float*)d_in[5];
    const float* lnw = (const float*)d_in[6];
    const float* lnb = (const float*)d_in[7];
    float* out = (float*)d_out;

    float *G;
    __nv_bfloat16 *xhi, *xlo, *ahi, *alo;
    __nv_bfloat16 *whi[5], *wlo[5];
    __nv_bfloat16 *qhi, *qlo, *khi, *klo, *vhi, *vlo;
    cudaGetSymbolAddress((void**)&G, g_G);
    cudaGetSymbolAddress((void**)&xhi, g_xhi);  cudaGetSymbolAddress((void**)&xlo, g_xlo);
    cudaGetSymbolAddress((void**)&ahi, g_ahi);  cudaGetSymbolAddress((void**)&alo, g_alo);
    cudaGetSymbolAddress((void**)&whi[0], g_wqhi); cudaGetSymbolAddress((void**)&wlo[0], g_wqlo);
    cudaGetSymbolAddress((void**)&whi[1], g_wkhi); cudaGetSymbolAddress((void**)&wlo[1], g_wklo);
    cudaGetSymbolAddress((void**)&whi[2], g_wvhi); cudaGetSymbolAddress((void**)&wlo[2], g_wvlo);
    cudaGetSymbolAddress((void**)&whi[3], g_wghi); cudaGetSymbolAddress((void**)&wlo[3], g_wglo);
    cudaGetSymbolAddress((void**)&whi[4], g_wohi); cudaGetSymbolAddress((void**)&wlo[4], g_wolo);
    cudaGetSymbolAddress((void**)&qhi, g_Qhi); cudaGetSymbolAddress((void**)&qlo, g_Qlo);
    cudaGetSymbolAddress((void**)&khi, g_Khi); cudaGetSymbolAddress((void**)&klo, g_Klo);
    cudaGetSymbolAddress((void**)&vhi, g_Vhi); cudaGetSymbolAddress((void**)&vlo, g_Vlo);

    static CUtensorMap h_maps[14];
    void* encPtr = nullptr;
    cudaDriverEntryPointQueryResult qres;
    cudaGetDriverEntryPoint("cuTensorMapEncodeTiled", &encPtr, cudaEnableDefault, &qres);
    EncodeFn enc = (EncodeFn)encPtr;
    make_map2d(enc, &h_maps[0], xhi, 128);
    make_map2d(enc, &h_maps[1], xlo, 128);
    make_map2d(enc, &h_maps[2], ahi, 128);
    make_map2d(enc, &h_maps[3], alo, 128);
    for (int p = 0; p < 5; p++) {
        make_map2d(enc, &h_maps[4 + 2 * p],     whi[p], 256);
        make_map2d(enc, &h_maps[4 + 2 * p + 1], wlo[p], 256);
    }
    cudaMemcpyToSymbolAsync(g_tmaps, h_maps, sizeof(h_maps), 0, cudaMemcpyHostToDevice, 0);
    CUtensorMap* tm;
    cudaGetSymbolAddress((void**)&tm, g_tmaps);

    cudaFuncSetAttribute(gemm3,   cudaFuncAttributeMaxDynamicSharedMemorySize, GEMM_SMEM);
    cudaFuncSetAttribute(gemm3x4, cudaFuncAttributeMaxDynamicSharedMemorySize, GEMM_SMEM);
    cudaFuncSetAttribute(retention_tc, cudaFuncAttributeMaxDynamicSharedMemorySize, AT_SMEM);

    cvt6<<<dim3(512, 6), 256>>>(x,  xhi,    xlo,
                                wq, whi[0], wlo[0],
                                wk, whi[1], wlo[1],
                                wv, whi[2], wlo[2],
                                wg, whi[3], wlo[3],
                                wo, whi[4], wlo[4]);

    gemm3x4<<<dim3(DIM / GBN, SEQ / GBM, 4), GTHREADS, GEMM_SMEM>>>(
        tm, qhi, qlo, khi, klo, vhi, vlo, G);

    retention_tc<<<dim3(SEQ / 64, NH), 256, AT_SMEM>>>();

    ln_silu_gate<<<SEQ, 256>>>(lnw, lnb, ahi, alo);

    gemm3<<<dim3(DIM / GBN, SEQ / GBM), GTHREADS, GEMM_SMEM>>>(tm + 2, tm + 3, tm + 12, tm + 13, out);
}

// round 17
// speedup vs baseline: 1.0770x; 1.0025x over previous
#include <cuda_runtime.h>
#include <cuda.h>
#include <cuda_bf16.h>
#include <math.h>
#include <cstdint>
#include <cstring>

#define SEQ 2048
#define DIM 2048
#define NH 16
#define HDIM 128

// ------------------------- scratch (device globals) -------------------------
__device__ float g_G[SEQ * DIM];
__device__ float g_Y[SEQ * DIM];

__device__ __nv_bfloat16 g_xhi[SEQ * DIM],  g_xlo[SEQ * DIM];
__device__ __nv_bfloat16 g_wqhi[DIM * DIM], g_wqlo[DIM * DIM];
__device__ __nv_bfloat16 g_wkhi[DIM * DIM], g_wklo[DIM * DIM];
__device__ __nv_bfloat16 g_wvhi[DIM * DIM], g_wvlo[DIM * DIM];
__device__ __nv_bfloat16 g_wghi[DIM * DIM], g_wglo[DIM * DIM];
__device__ __nv_bfloat16 g_wohi[DIM * DIM], g_wolo[DIM * DIM];
__device__ __nv_bfloat16 g_Qhi[SEQ * DIM],  g_Qlo[SEQ * DIM];
__device__ __nv_bfloat16 g_Khi[SEQ * DIM],  g_Klo[SEQ * DIM];
__device__ __nv_bfloat16 g_Vhi[SEQ * DIM],  g_Vlo[SEQ * DIM];
__device__ __nv_bfloat16 g_ahi[SEQ * DIM],  g_alo[SEQ * DIM];

__device__ CUtensorMap g_tmaps[14];

// ------------------------- helpers -------------------------
__device__ __forceinline__ uint32_t smem_u32(const void* p) {
    uint32_t a;
    asm("{ .reg .u64 t; cvta.to.shared.u64 t, %1; cvt.u32.u64 %0, t; }" : "=r"(a) : "l"(p));
    return a;
}
__device__ __forceinline__ void cp16(uint32_t dst, const void* src) {
    asm volatile("cp.async.cg.shared.global [%0], [%1], 16;" :: "r"(dst), "l"(src));
}
__device__ __forceinline__ void ldx4(uint32_t* r, uint32_t addr) {
    asm volatile("ldmatrix.sync.aligned.m8n8.x4.shared.b16 {%0,%1,%2,%3}, [%4];"
                 : "=r"(r[0]), "=r"(r[1]), "=r"(r[2]), "=r"(r[3]) : "r"(addr));
}
__device__ __forceinline__ void ldx4t(uint32_t* r, uint32_t addr) {
    asm volatile("ldmatrix.sync.aligned.m8n8.x4.trans.shared.b16 {%0,%1,%2,%3}, [%4];"
                 : "=r"(r[0]), "=r"(r[1]), "=r"(r[2]), "=r"(r[3]) : "r"(addr));
}
__device__ __forceinline__ void mma16816(float* c, const uint32_t* a, uint32_t b0, uint32_t b1) {
    asm volatile(
        "mma.sync.aligned.m16n8k16.row.col.f32.bf16.bf16.f32 "
        "{%0,%1,%2,%3}, {%4,%5,%6,%7}, {%8,%9}, {%0,%1,%2,%3};"
        : "+f"(c[0]), "+f"(c[1]), "+f"(c[2]), "+f"(c[3])
        : "r"(a[0]), "r"(a[1]), "r"(a[2]), "r"(a[3]), "r"(b0), "r"(b1));
}

#define MBARRIER_INIT(addr, cnt) \
    asm volatile("mbarrier.init.shared.b64 [%0], %1;" :: "r"(addr), "r"(cnt) : "memory")
#define MBARRIER_ARRIVE(addr) \
    asm volatile("mbarrier.arrive.shared.b64 _, [%0];" :: "r"(addr) : "memory")
#define MBARRIER_EXPECT_TX(addr, bytes) \
    asm volatile("mbarrier.arrive.expect_tx.shared.b64 _, [%0], %1;" :: "r"(addr), "r"(bytes) : "memory")
#define MBARRIER_WAIT_PARITY(addr, par) do { \
    uint32_t _m = (addr); uint32_t _p = (par); uint32_t _d; \
    asm volatile("{ .reg .pred p; mbarrier.try_wait.parity.acquire.cta.shared::cta.b64 p, [%1], %2; selp.b32 %0,1,0,p; }" \
        : "=r"(_d) : "r"(_m), "r"(_p) : "memory"); \
    if (!_d) { \
        asm volatile("{ .reg .pred P1; WL_%=: mbarrier.try_wait.parity.acquire.cta.shared::cta.b64 P1, [%0], %1, 0x989680; @P1 bra.uni WD_%=; bra.uni WL_%=; WD_%=: }" \
            :: "r"(_m), "r"(_p) : "memory"); \
    } \
} while (0)
#define TMA_LOAD_2D(smem_addr, map, cx, cy, mbar) \
    asm volatile("cp.async.bulk.tensor.2d.shared::cta.global.tile.mbarrier::complete_tx::bytes " \
                 "[%0], [%1, {%2, %3}], [%4];" \
                 :: "r"(smem_addr), "l"(map), "r"(cx), "r"(cy), "r"(mbar) : "memory")

// ---------------------------------------------------------------------------
// Fused 3-pass hi/lo bf16 GEMM body (TN). Tile 128x256, BK=64, 512 thr (4x4).
// TMA + full/empty mbarrier ring; per-warp (lane0) empty arrives, count=16.
// ---------------------------------------------------------------------------
static constexpr int GBM = 128, GBN = 256, GBK = 64;
static constexpr int GTHREADS = 512;
static constexpr int NCH = DIM / GBK;
static constexpr int OF_AH = 0;
static constexpr int OF_AL = 16384;
static constexpr int OF_BH = 32768;
static constexpr int OF_BL = 65536;
static constexpr int GBUF = 98304;
static constexpr int GEMM_SMEM = 2 * GBUF + 64;

__device__ __forceinline__ void tma_chunk(uint32_t buf, const CUtensorMap* mAh,
                                          const CUtensorMap* mAl, const CUtensorMap* mBh,
                                          const CUtensorMap* mBl, int m0, int n0, int kc,
                                          uint32_t bar) {
    MBARRIER_EXPECT_TX(bar, (uint32_t)GBUF);
    TMA_LOAD_2D(buf + OF_AH, mAh, kc, m0, bar);
    TMA_LOAD_2D(buf + OF_AL, mAl, kc, m0, bar);
    TMA_LOAD_2D(buf + OF_BH, mBh, kc, n0, bar);
    TMA_LOAD_2D(buf + OF_BL, mBl, kc, n0, bar);
}

__device__ __forceinline__ void gemm3_body(const CUtensorMap* mAh, const CUtensorMap* mAl,
                                           const CUtensorMap* mBh, const CUtensorMap* mBl,
                                           float* C, __nv_bfloat16* Chi, __nv_bfloat16* Clo,
                                           int mode, char* smem, int m0, int n0) {
    uint32_t sb = smem_u32(smem);
    uint32_t full0 = sb + 2 * GBUF, full1 = full0 + 8;
    uint32_t empty0 = full1 + 8, empty1 = empty0 + 8;
    int tid = threadIdx.x;
    int wid = tid >> 5, lane = tid & 31;
    int wm = wid & 3, wn = wid >> 2;

    if (tid == 0) {
        asm volatile("prefetch.tensormap [%0];" :: "l"(mAh));
        asm volatile("prefetch.tensormap [%0];" :: "l"(mAl));
        asm volatile("prefetch.tensormap [%0];" :: "l"(mBh));
        asm volatile("prefetch.tensormap [%0];" :: "l"(mBl));
        MBARRIER_INIT(full0, 1);
        MBARRIER_INIT(full1, 1);
        MBARRIER_INIT(empty0, 16);
        MBARRIER_INIT(empty1, 16);
    }
    __syncthreads();
    if (tid == 0) {
        tma_chunk(sb, mAh, mAl, mBh, mBl, m0, n0, 0, full0);
        tma_chunk(sb + GBUF, mAh, mAl, mBh, mBl, m0, n0, GBK, full1);
    }

    int a_mh = (lane >> 3) & 1, a_kh = lane >> 4, lr = lane & 7;
    uint32_t aOff[2]; int aR7[2];
#pragma unroll
    for (int i = 0; i < 2; i++) {
        int row = wm * 32 + i * 16 + a_mh * 8 + lr;
        aOff[i] = row * 128; aR7[i] = row & 7;
    }
    int b_jl = lane >> 4, b_kh = (lane >> 3) & 1;
    uint32_t bOff[4]; int bR7[4];
#pragma unroll
    for (int p = 0; p < 4; p++) {
        int row = wn * 64 + p * 16 + b_jl * 8 + lr;
        bOff[p] = row * 128; bR7[p] = row & 7;
    }

    float acc[2][8][4];
#pragma unroll
    for (int i = 0; i < 2; i++)
#pragma unroll
        for (int j = 0; j < 8; j++)
#pragma unroll
            for (int q = 0; q < 4; q++) acc[i][j][q] = 0.f;

    for (int t = 0; t < NCH; t++) {
        uint32_t full  = (t & 1) ? full1 : full0;
        uint32_t empty = (t & 1) ? empty1 : empty0;
        MBARRIER_WAIT_PARITY(full, (t >> 1) & 1);

        uint32_t buf = sb + (t & 1) * GBUF;
#pragma unroll
        for (int ks = 0; ks < 4; ks++) {
            int ca = ks * 2 + a_kh;
            int cb = ks * 2 + b_kh;
            uint32_t ah[2][4], al[2][4];
#pragma unroll
            for (int i = 0; i < 2; i++) {
                ldx4(ah[i], buf + OF_AH + aOff[i] + (((uint32_t)(ca ^ aR7[i])) << 4));
                ldx4(al[i], buf + OF_AL + aOff[i] + (((uint32_t)(ca ^ aR7[i])) << 4));
            }
#pragma unroll
            for (int ph = 0; ph < 2; ph++) {
                uint32_t bh[2][4], bl[2][4];
#pragma unroll
                for (int p2 = 0; p2 < 2; p2++) {
                    int p = ph * 2 + p2;
                    ldx4(bh[p2], buf + OF_BH + bOff[p] + (((uint32_t)(cb ^ bR7[p])) << 4));
                    ldx4(bl[p2], buf + OF_BL + bOff[p] + (((uint32_t)(cb ^ bR7[p])) << 4));
                }
#pragma unroll
                for (int i = 0; i < 2; i++)
#pragma unroll
                    for (int j4 = 0; j4 < 4; j4++) {
                        int j = ph * 4 + j4;
                        int p2 = j4 >> 1, jl = j4 & 1;
                        mma16816(acc[i][j], ah[i], bh[p2][2 * jl], bh[p2][2 * jl + 1]);
                        mma16816(acc[i][j], ah[i], bl[p2][2 * jl], bl[p2][2 * jl + 1]);
                        mma16816(acc[i][j], al[i], bh[p2][2 * jl], bh[p2][2 * jl + 1]);
                    }
            }
        }

        if (lane == 0) MBARRIER_ARRIVE(empty);   // per-warp consume signal (count 16)
        if (t + 2 < NCH && tid == 0) {
            MBARRIER_WAIT_PARITY(empty, (t >> 1) & 1);
            tma_chunk(buf, mAh, mAl, mBh, mBl, m0, n0, (t + 2) * GBK, full);
        }
    }

    int qr = lane >> 2, qc = (lane & 3) * 2;
#pragma unroll
    for (int i = 0; i < 2; i++) {
        int mrow = m0 + wm * 32 + i * 16 + qr;
#pragma unroll
        for (int j = 0; j < 8; j++) {
            size_t base = (size_t)mrow * DIM + n0 + wn * 64 + j * 8 + qc;
            if (mode == 0) {
                C[base]               = acc[i][j][0];
                C[base + 1]           = acc[i][j][1];
                C[base + 8 * DIM]     = acc[i][j][2];
                C[base + 8 * DIM + 1] = acc[i][j][3];
            } else {
#pragma unroll
                for (int h2 = 0; h2 < 2; h2++) {
                    float v0 = acc[i][j][h2 * 2], v1 = acc[i][j][h2 * 2 + 1];
                    __nv_bfloat16 h0 = __float2bfloat16(v0), h1 = __float2bfloat16(v1);
                    __nv_bfloat16 l0 = __float2bfloat16(v0 - __bfloat162float(h0));
                    __nv_bfloat16 l1 = __float2bfloat16(v1 - __bfloat162float(h1));
                    size_t bb = base + h2 * 8 * DIM;
                    *(__nv_bfloat162*)(Chi + bb) = __nv_bfloat162(h0, h1);
                    *(__nv_bfloat162*)(Clo + bb) = __nv_bfloat162(l0, l1);
                }
            }
        }
    }
}

// final wo projection: single GEMM
__global__ __launch_bounds__(GTHREADS, 1) void gemm3(const CUtensorMap* __restrict__ mAh,
                                                     const CUtensorMap* __restrict__ mAl,
                                                     const CUtensorMap* __restrict__ mBh,
                                                     const CUtensorMap* __restrict__ mBl,
                                                     float* __restrict__ C) {
    extern __shared__ char smem[];
    gemm3_body(mAh, mAl, mBh, mBl, C, nullptr, nullptr, 0, smem,
               blockIdx.y * GBM, blockIdx.x * GBN);
}

// merged Q/K/V/G projections: grid (8, 16, 4), z selects weight/output.
__global__ __launch_bounds__(GTHREADS, 1) void gemm3x4(
    const CUtensorMap* __restrict__ tm,
    __nv_bfloat16* __restrict__ qhi, __nv_bfloat16* __restrict__ qlo,
    __nv_bfloat16* __restrict__ khi, __nv_bfloat16* __restrict__ klo,
    __nv_bfloat16* __restrict__ vhi, __nv_bfloat16* __restrict__ vlo,
    float* __restrict__ G) {
    extern __shared__ char smem[];
    int z = blockIdx.z;
    const CUtensorMap* mBh = tm + 4 + 2 * z;
    const CUtensorMap* mBl = tm + 5 + 2 * z;
    __nv_bfloat16 *Chi = nullptr, *Clo = nullptr;
    float* Cf = nullptr;
    int mode;
    if (z == 0)      { Chi = qhi; Clo = qlo; mode = 1; }
    else if (z == 1) { Chi = khi; Clo = klo; mode = 1; }
    else if (z == 2) { Chi = vhi; Clo = vlo; mode = 1; }
    else             { Cf = G;               mode = 0; }
    gemm3_body(tm + 0, tm + 1, mBh, mBl, Cf, Chi, Clo, mode, smem,
               blockIdx.y * GBM, blockIdx.x * GBN);
}

// ---------------------------------------------------------------------------
// fp32 -> bf16 hi/lo, all 6 tensors in one launch; 8 float4/thread (MLP=8)
// ---------------------------------------------------------------------------
__global__ __launch_bounds__(256) void cvt6(
    const float* s0, __nv_bfloat16* h0, __nv_bfloat16* l0,
    const float* s1, __nv_bfloat16* h1, __nv_bfloat16* l1,
    const float* s2, __nv_bfloat16* h2, __nv_bfloat16* l2,
    const float* s3, __nv_bfloat16* h3, __nv_bfloat16* l3,
    const float* s4, __nv_bfloat16* h4, __nv_bfloat16* l4,
    const float* s5, __nv_bfloat16* h5, __nv_bfloat16* l5) {
    const float* s; __nv_bfloat16 *hi, *lo;
    switch (blockIdx.y) {
        case 0: s = s0; hi = h0; lo = l0; break;
        case 1: s = s1; hi = h1; lo = l1; break;
        case 2: s = s2; hi = h2; lo = l2; break;
        case 3: s = s3; hi = h3; lo = l3; break;
        case 4: s = s4; hi = h4; lo = l4; break;
        default: s = s5; hi = h5; lo = l5; break;
    }
    int base = blockIdx.x * 2048 + threadIdx.x;
    float4 v[8];
#pragma unroll
    for (int u = 0; u < 8; u++) v[u] = ((const float4*)s)[base + u * 256];
#pragma unroll
    for (int u = 0; u < 8; u++) {
        int i = base + u * 256;
        __nv_bfloat16 a0 = __float2bfloat16(v[u].x), a1 = __float2bfloat16(v[u].y);
        __nv_bfloat16 a2 = __float2bfloat16(v[u].z), a3 = __float2bfloat16(v[u].w);
        __nv_bfloat16 b0 = __float2bfloat16(v[u].x - __bfloat162float(a0));
        __nv_bfloat16 b1 = __float2bfloat16(v[u].y - __bfloat162float(a1));
        __nv_bfloat16 b2 = __float2bfloat16(v[u].z - __bfloat162float(a2));
        __nv_bfloat16 b3 = __float2bfloat16(v[u].w - __bfloat162float(a3));
        ((__nv_bfloat162*)hi)[2 * i]     = __nv_bfloat162(a0, a1);
        ((__nv_bfloat162*)hi)[2 * i + 1] = __nv_bfloat162(a2, a3);
        ((__nv_bfloat162*)lo)[2 * i]     = __nv_bfloat162(b0, b1);
        ((__nv_bfloat162*)lo)[2 * i + 1] = __nv_bfloat162(b2, b3);
    }
}

// ---------------------------------------------------------------------------
// Tensor-core retention attention (BI=BJ=64, 8 warps, K/V double-buffered).
// grid (32 i-tiles, 16 heads), 256 threads. (round-11 version — known good)
// ---------------------------------------------------------------------------
static constexpr int KVBUF = 65536;
static constexpr int OQH = 0, OQL = 16384;
static constexpr int OKV = 32768;
static constexpr int OKH = 0, OKL = 16384, OVH = 32768, OVL = 49152;
static constexpr int OSH = 163840, OSL = 172032;
static constexpr int AT_SMEM = 180224;

__device__ __forceinline__ void at_load_kv(uint32_t kvbase,
                                           const __nv_bfloat16* Khg, const __nv_bfloat16* Klg,
                                           const __nv_bfloat16* Vhg, const __nv_bfloat16* Vlg,
                                           int j0, int tid) {
#pragma unroll
    for (int l = 0; l < 8; l++) {
        int idx = tid + l * 256;
        int arr = idx >> 10, ct = (idx >> 9) & 1, r = (idx >> 3) & 63, c = idx & 7;
        const __nv_bfloat16* src = (arr ? Klg : Khg) + (size_t)(j0 + r) * DIM + ct * 64 + c * 8;
        uint32_t dst = kvbase + (arr ? OKL : OKH) + ct * 8192 + r * 128 + (((c ^ (r & 7))) << 4);
        cp16(dst, src);
    }
#pragma unroll
    for (int l = 0; l < 8; l++) {
        int idx = tid + l * 256;
        int arr = idx >> 10, r = (idx >> 4) & 63, dc = idx & 15;
        const __nv_bfloat16* src = (arr ? Vlg : Vhg) + (size_t)(j0 + r) * DIM + dc * 8;
        uint32_t dst = kvbase + (arr ? OVL : OVH) + r * 256 + (((dc ^ (r & 7))) << 4);
        cp16(dst, src);
    }
}

__global__ __launch_bounds__(256, 1) void retention_tc() {
    extern __shared__ char smem[];
    uint32_t sb = smem_u32(smem);

    int head = blockIdx.y;
    int it = gridDim.x - 1 - blockIdx.x;
    int i0 = it * 64;
    int tid = threadIdx.x, lane = tid & 31, wid = tid >> 5;
    int wm = wid & 1, wn = wid >> 1;

    const float lg0 = -3.4657359027997265f;
    const float lg1 = -6.2383246250395075f;
    float gamma = 1.0f - expf(lg0 + (lg1 - lg0) * ((float)head * (1.0f / 15.0f)));
    float log2g = log2f(gamma);
    const float scale = 0.088388347648318447f;

    const __nv_bfloat16* Qhg = g_Qhi + head * HDIM;
    const __nv_bfloat16* Qlg = g_Qlo + head * HDIM;
    const __nv_bfloat16* Khg = g_Khi + head * HDIM;
    const __nv_bfloat16* Klg = g_Klo + head * HDIM;
    const __nv_bfloat16* Vhg = g_Vhi + head * HDIM;
    const __nv_bfloat16* Vlg = g_Vlo + head * HDIM;

    int qr = lane >> 2, qc = (lane & 3) * 2;
    int a_mh = (lane >> 3) & 1, a_kh = lane >> 4, lr = lane & 7;
    int b_jl = lane >> 4, b_kh = (lane >> 3) & 1;
    int v_m = (lane >> 3) & 1, v_g = lane >> 4;

    uint32_t aOff[2]; int aR7[2];
#pragma unroll
    for (int i = 0; i < 2; i++) {
        int row = wm * 32 + i * 16 + a_mh * 8 + lr;
        aOff[i] = row * 128; aR7[i] = row & 7;
    }
    int brow = wn * 16 + b_jl * 8 + lr;
    uint32_t bOff = brow * 128; int bR7 = brow & 7;

    float colfac[2][2];
#pragma unroll
    for (int jf = 0; jf < 2; jf++)
#pragma unroll
        for (int lb = 0; lb < 2; lb++) {
            int dj = wn * 16 + jf * 8 + qc + lb;
            colfac[jf][lb] = exp2f(-log2g * (float)dj) * scale;
        }

#pragma unroll
    for (int l = 0; l < 8; l++) {
        int idx = tid + l * 256;
        int arr = idx >> 10, ct = (idx >> 9) & 1, r = (idx >> 3) & 63, c = idx & 7;
        const __nv_bfloat16* src = (arr ? Qlg : Qhg) + (size_t)(i0 + r) * DIM + ct * 64 + c * 8;
        uint32_t dst = sb + (arr ? OQL : OQH) + ct * 8192 + r * 128 + (((c ^ (r & 7))) << 4);
        cp16(dst, src);
    }
    at_load_kv(sb + OKV, Khg, Klg, Vhg, Vlg, 0, tid);
    asm volatile("cp.async.commit_group;" ::: "memory");

    float yacc[2][4][4];
#pragma unroll
    for (int i = 0; i < 2; i++)
#pragma unroll
        for (int t = 0; t < 4; t++)
#pragma unroll
            for (int q = 0; q < 4; q++) yacc[i][t][q] = 0.f;

    for (int jt = 0; jt <= it; jt++) {
        int j0 = jt * 64;
        uint32_t kvb = sb + OKV + (jt & 1) * KVBUF;

        asm volatile("cp.async.wait_group 0;" ::: "memory");
        __syncthreads();

        if (jt < it) {
            at_load_kv(sb + OKV + ((jt + 1) & 1) * KVBUF, Khg, Klg, Vhg, Vlg, j0 + 64, tid);
            asm volatile("cp.async.commit_group;" ::: "memory");
        }

        float acc1[2][2][4];
#pragma unroll
        for (int i = 0; i < 2; i++)
#pragma unroll
            for (int j = 0; j < 2; j++)
#pragma unroll
                for (int q = 0; q < 4; q++) acc1[i][j][q] = 0.f;

#pragma unroll
        for (int ct = 0; ct < 2; ct++) {
#pragma unroll
            for (int ks = 0; ks < 4; ks++) {
                int ca = ks * 2 + a_kh;
                int cb = ks * 2 + b_kh;
                uint32_t qh[2][4], ql[2][4], bh[4], bl[4];
#pragma unroll
                for (int i = 0; i < 2; i++) {
                    ldx4(qh[i], sb + OQH + ct * 8192 + aOff[i] + (((uint32_t)(ca ^ aR7[i])) << 4));
                    ldx4(ql[i], sb + OQL + ct * 8192 + aOff[i] + (((uint32_t)(ca ^ aR7[i])) << 4));
                }
                ldx4(bh, kvb + OKH + ct * 8192 + bOff + (((uint32_t)(cb ^ bR7)) << 4));
                ldx4(bl, kvb + OKL + ct * 8192 + bOff + (((uint32_t)(cb ^ bR7)) << 4));
#pragma unroll
                for (int i = 0; i < 2; i++)
#pragma unroll
                    for (int j = 0; j < 2; j++) {
                        mma16816(acc1[i][j], qh[i], bh[2 * j], bh[2 * j + 1]);
                        mma16816(acc1[i][j], qh[i], bl[2 * j], bl[2 * j + 1]);
                        mma16816(acc1[i][j], ql[i], bh[2 * j], bh[2 * j + 1]);
                    }
            }
        }

        float rowfac[2][2];
#pragma unroll
        for (int i = 0; i < 2; i++)
#pragma unroll
            for (int h = 0; h < 2; h++) {
                int rrel = i0 - j0 + wm * 32 + i * 16 + qr + h * 8;
                rowfac[i][h] = exp2f(log2g * (float)rrel);
            }
#pragma unroll
        for (int i = 0; i < 2; i++)
#pragma unroll
            for (int j = 0; j < 2; j++)
#pragma unroll
                for (int h = 0; h < 2; h++) {
                    int row = wm * 32 + i * 16 + qr + h * 8;
                    int col = wn * 16 + j * 8 + qc;
                    int diff0 = (i0 + row) - (j0 + col);
                    float v0 = (diff0 >= 0) ? acc1[i][j][h * 2 + 0] * rowfac[i][h] * colfac[j][0] : 0.f;
                    float v1 = (diff0 >= 1) ? acc1[i][j][h * 2 + 1] * rowfac[i][h] * colfac[j][1] : 0.f;
                    __nv_bfloat16 h0 = __float2bfloat16(v0), h1 = __float2bfloat16(v1);
                    __nv_bfloat16 l0 = __float2bfloat16(v0 - __bfloat162float(h0));
                    __nv_bfloat16 l1 = __float2bfloat16(v1 - __bfloat162float(h1));
                    uint32_t off = row * 128 + ((((col >> 3) ^ (row & 7))) << 4) + (col & 7) * 2;
                    *(__nv_bfloat162*)(smem + OSH + off) = __nv_bfloat162(h0, h1);
                    *(__nv_bfloat162*)(smem + OSL + off) = __nv_bfloat162(l0, l1);
                }
        __syncthreads();

#pragma unroll
        for (int ks = 0; ks < 4; ks++) {
            int ca = ks * 2 + a_kh;
            uint32_t sh[2][4], sl[2][4], vh[2][4], vl[2][4];
#pragma unroll
            for (int i = 0; i < 2; i++) {
                ldx4(sh[i], sb + OSH + aOff[i] + (((uint32_t)(ca ^ aR7[i])) << 4));
                ldx4(sl[i], sb + OSL + aOff[i] + (((uint32_t)(ca ^ aR7[i])) << 4));
            }
            int vrow = ks * 16 + v_m * 8 + lr;
#pragma unroll
            for (int g = 0; g < 2; g++) {
                int dc = wn * 4 + g * 2 + v_g;
                uint32_t vo = vrow * 256 + (((uint32_t)(dc ^ (vrow & 7))) << 4);
                ldx4t(vh[g], kvb + OVH + vo);
                ldx4t(vl[g], kvb + OVL + vo);
            }
#pragma unroll
            for (int i = 0; i < 2; i++)
#pragma unroll
                for (int t = 0; t < 4; t++) {
                    int g = t >> 1, s2 = (t & 1) * 2;
                    mma16816(yacc[i][t], sh[i], vh[g][s2], vh[g][s2 + 1]);
                    mma16816(yacc[i][t], sh[i], vl[g][s2], vl[g][s2 + 1]);
                    mma16816(yacc[i][t], sl[i], vh[g][s2], vh[g][s2 + 1]);
                }
        }
    }

#pragma unroll
    for (int i = 0; i < 2; i++) {
        int row = i0 + wm * 32 + i * 16 + qr;
#pragma unroll
        for (int t = 0; t < 4; t++) {
            float* yp = g_Y + (size_t)row * DIM + head * HDIM + wn * 32 + t * 8 + qc;
            *(float2*)yp = make_float2(yacc[i][t][0], yacc[i][t][1]);
            *(float2*)(yp + 8 * DIM) = make_float2(yacc[i][t][2], yacc[i][t][3]);
        }
    }
}

// ---------------------------------------------------------------------------
// LayerNorm(Y) * silu(G) -> bf16 hi + lo arrays.
// All loads (y, g, lnw, lnb) issued up-front so they overlap the reduction.
// ---------------------------------------------------------------------------
__global__ __launch_bounds__(256) void ln_silu_gate(const float* __restrict__ lnw,
                                                    const float* __restrict__ lnb,
                                                    __nv_bfloat16* __restrict__ ohi,
                                                    __nv_bfloat16* __restrict__ olo) {
    int row = blockIdx.x;
    const float* y = g_Y + (size_t)row * DIM;
    const float* g = g_G + (size_t)row * DIM;
    int tid = threadIdx.x;

    float vals[8];
    float4 gv[2], wv[2], bv[2];
    float s = 0.f, ss = 0.f;
#pragma unroll
    for (int i = 0; i < 2; i++) {
        int c0 = tid * 4 + i * 1024;
        float4 v = *(const float4*)(y + c0);
        gv[i] = *(const float4*)(g + c0);
        wv[i] = *(const float4*)(lnw + c0);
        bv[i] = *(const float4*)(lnb + c0);
        vals[i * 4 + 0] = v.x; vals[i * 4 + 1] = v.y;
        vals[i * 4 + 2] = v.z; vals[i * 4 + 3] = v.w;
        s += v.x + v.y + v.z + v.w;
        ss += v.x * v.x + v.y * v.y + v.z * v.z + v.w * v.w;
    }
#pragma unroll
    for (int off = 16; off > 0; off >>= 1) {
        s += __shfl_xor_sync(0xFFFFFFFFu, s, off);
        ss += __shfl_xor_sync(0xFFFFFFFFu, ss, off);
    }
    __shared__ float rs[8], rss[8];
    if ((tid & 31) == 0) { rs[tid >> 5] = s; rss[tid >> 5] = ss; }
    __syncthreads();
    s = 0.f; ss = 0.f;
#pragma unroll
    for (int i = 0; i < 8; i++) { s += rs[i]; ss += rss[i]; }

    float mu = s * (1.0f / DIM);
    float var = ss * (1.0f / DIM) - mu * mu;
    float rstd = rsqrtf(var + 1e-5f);

#pragma unroll
    for (int i = 0; i < 2; i++) {
        int c0 = tid * 4 + i * 1024;
        float o[4];
        o[0] = ((vals[i * 4 + 0] - mu) * rstd * wv[i].x + bv[i].x) * (gv[i].x / (1.0f + expf(-gv[i].x)));
        o[1] = ((vals[i * 4 + 1] - mu) * rstd * wv[i].y + bv[i].y) * (gv[i].y / (1.0f + expf(-gv[i].y)));
        o[2] = ((vals[i * 4 + 2] - mu) * rstd * wv[i].z + bv[i].z) * (gv[i].z / (1.0f + expf(-gv[i].z)));
        o[3] = ((vals[i * 4 + 3] - mu) * rstd * wv[i].w + bv[i].w) * (gv[i].w / (1.0f + expf(-gv[i].w)));
        __nv_bfloat16 h[4], l[4];
#pragma unroll
        for (int j = 0; j < 4; j++) {
            h[j] = __float2bfloat16(o[j]);
            l[j] = __float2bfloat16(o[j] - __bfloat162float(h[j]));
        }
        size_t base = (size_t)row * DIM + c0;
        *(__nv_bfloat162*)(ohi + base)     = __nv_bfloat162(h[0], h[1]);
        *(__nv_bfloat162*)(ohi + base + 2) = __nv_bfloat162(h[2], h[3]);
        *(__nv_bfloat162*)(olo + base)     = __nv_bfloat162(l[0], l[1]);
        *(__nv_bfloat162*)(olo + base + 2) = __nv_bfloat162(l[2], l[3]);
    }
}

// ---------------------------------------------------------------------------
typedef CUresult (*EncodeFn)(CUtensorMap*, CUtensorMapDataType, cuuint32_t, void*,
                             const cuuint64_t*, const cuuint64_t*, const cuuint32_t*,
                             const cuuint32_t*, CUtensorMapInterleave, CUtensorMapSwizzle,
                             CUtensorMapL2promotion, CUtensorMapFloatOOBfill);

static void make_map2d(EncodeFn enc, CUtensorMap* m, void* ptr, uint32_t box_rows) {
    cuuint64_t dims[2] = {DIM, SEQ};
    cuuint64_t strides[1] = {DIM * 2};
    cuuint32_t box[2] = {64, box_rows};
    cuuint32_t es[2] = {1, 1};
    enc(m, CU_TENSOR_MAP_DATA_TYPE_BFLOAT16, 2, ptr, dims, strides, box, es,
        CU_TENSOR_MAP_INTERLEAVE_NONE, CU_TENSOR_MAP_SWIZZLE_128B,
        CU_TENSOR_MAP_L2_PROMOTION_L2_128B, CU_TENSOR_MAP_FLOAT_OOB_FILL_NONE);
}

extern "C" void kernel_launch(void* const* d_in, const int* in_sizes, int n_in,
                              void* d_out, int out_size) {
    const float* x   = (const float*)d_in[0];
    const float* wq  = (const float*)d_in[1];
    const float* wk  = (const float*)d_in[2];
    const float* wv  = (const float*)d_in[3];
    const float* wg  = (const float*)d_in[4];
    const float* wo  = (const float*)d_in[5];
    const float* lnw = (const float*)d_in[6];
    const float* lnb = (const float*)d_in[7];
    float* out = (float*)d_out;

    float *G;
    __nv_bfloat16 *xhi, *xlo, *ahi, *alo;
    __nv_bfloat16 *whi[5], *wlo[5];
    __nv_bfloat16 *qhi, *qlo, *khi, *klo, *vhi, *vlo;
    cudaGetSymbolAddress((void**)&G, g_G);
    cudaGetSymbolAddress((void**)&xhi, g_xhi);  cudaGetSymbolAddress((void**)&xlo, g_xlo);
    cudaGetSymbolAddress((void**)&ahi, g_ahi);  cudaGetSymbolAddress((void**)&alo, g_alo);
    cudaGetSymbolAddress((void**)&whi[0], g_wqhi); cudaGetSymbolAddress((void**)&wlo[0], g_wqlo);
    cudaGetSymbolAddress((void**)&whi[1], g_wkhi); cudaGetSymbolAddress((void**)&wlo[1], g_wklo);
    cudaGetSymbolAddress((void**)&whi[2], g_wvhi); cudaGetSymbolAddress((void**)&wlo[2], g_wvlo);
    cudaGetSymbolAddress((void**)&whi[3], g_wghi); cudaGetSymbolAddress((void**)&wlo[3], g_wglo);
    cudaGetSymbolAddress((void**)&whi[4], g_wohi); cudaGetSymbolAddress((void**)&wlo[4], g_wolo);
    cudaGetSymbolAddress((void**)&qhi, g_Qhi); cudaGetSymbolAddress((void**)&qlo, g_Qlo);
    cudaGetSymbolAddress((void**)&khi, g_Khi); cudaGetSymbolAddress((void**)&klo, g_Klo);
    cudaGetSymbolAddress((void**)&vhi, g_Vhi); cudaGetSymbolAddress((void**)&vlo, g_Vlo);

    static CUtensorMap h_maps[14];
    void* encPtr = nullptr;
    cudaDriverEntryPointQueryResult qres;
    cudaGetDriverEntryPoint("cuTensorMapEncodeTiled", &encPtr, cudaEnableDefault, &qres);
    EncodeFn enc = (EncodeFn)encPtr;
    make_map2d(enc, &h_maps[0], xhi, 128);
    make_map2d(enc, &h_maps[1], xlo, 128);
    make_map2d(enc, &h_maps[2], ahi, 128);
    make_map2d(enc, &h_maps[3], alo, 128);
    for (int p = 0; p < 5; p++) {
        make_map2d(enc, &h_maps[4 + 2 * p],     whi[p], 256);
        make_map2d(enc, &h_maps[4 + 2 * p + 1], wlo[p], 256);
    }
    cudaMemcpyToSymbolAsync(g_tmaps, h_maps, sizeof(h_maps), 0, cudaMemcpyHostToDevice, 0);
    CUtensorMap* tm;
    cudaGetSymbolAddress((void**)&tm, g_tmaps);

    cudaFuncSetAttribute(gemm3,   cudaFuncAttributeMaxDynamicSharedMemorySize, GEMM_SMEM);
    cudaFuncSetAttribute(gemm3x4, cudaFuncAttributeMaxDynamicSharedMemorySize, GEMM_SMEM);
    cudaFuncSetAttribute(retention_tc, cudaFuncAttributeMaxDynamicSharedMemorySize, AT_SMEM);

    cvt6<<<dim3(512, 6), 256>>>(x,  xhi,    xlo,
                                wq, whi[0], wlo[0],
                                wk, whi[1], wlo[1],
                                wv, whi[2], wlo[2],
                                wg, whi[3], wlo[3],
                                wo, whi[4], wlo[4]);

    gemm3x4<<<dim3(DIM / GBN, SEQ / GBM, 4), GTHREADS, GEMM_SMEM>>>(
        tm, qhi, qlo, khi, klo, vhi, vlo, G);

    retention_tc<<<dim3(SEQ / 64, NH), 256, AT_SMEM>>>();

    ln_silu_gate<<<SEQ, 256>>>(lnw, lnb, ahi, alo);

    gemm3<<<dim3(DIM / GBN, SEQ / GBM), GTHREADS, GEMM_SMEM>>>(tm + 2, tm + 3, tm + 12, tm + 13, out);
}